// round 7
// baseline (speedup 1.0000x reference)
#include <cuda_runtime.h>
#include <math.h>

// Problem dims (fixed by the dataset)
constexpr int Bb = 16, Ll = 512, Wn = 8, Ee = 200, Dd = 768;
constexpr int M1 = Bb * Ll * Wn;   // 65536 (B*L*W) rows for GEMM1
constexpr int M2 = Bb * Ll;        // 8192  (B*L)   rows for the rest

// Scratch (no cudaMalloc allowed) — ~276 MB of __device__ globals.
__device__ float g_H[(size_t)M1 * Dd];   // tanh(WE @ Wt^T + bt)      [65536,768]
__device__ float g_C[Dd * Dd];           // attn_W @ Ww               [768,768]
__device__ float g_R[M2 * Dd];           // LO @ C                    [8192,768]
__device__ float g_G[M2 * Dd];           // sum_w alpha_w * H         [8192,768]
__device__ float g_WTD[M2 * Dd];         // G @ Ww^T + bw             [8192,768]

// ---------------------------------------------------------------------------
// Generic tiled fp32 SGEMM.
//   out[m,n] = act( sum_k A[m,k] * B'(k,n) + bias[n] )
//   B'(k,n) = BT ? B[n*K + k] : B[k*N + n]
// M, N must be multiples of BM, BN. K may be ragged (guarded).
// ---------------------------------------------------------------------------
template <int BM, int BN, int BK, int TM, int TN, bool BT, bool DO_TANH>
__global__ void __launch_bounds__((BM / TM) * (BN / TN))
sgemm_kernel(const float* __restrict__ A, const float* __restrict__ B,
             const float* __restrict__ bias, float* __restrict__ Cout,
             int M, int N, int K)
{
    constexpr int THREADS = (BM / TM) * (BN / TN);
    __shared__ float As[BK][BM];
    __shared__ float Bs[BK][BN];

    const int tid = threadIdx.x;
    const int m0  = blockIdx.y * BM;
    const int n0  = blockIdx.x * BN;

    const int tx = tid % (BN / TN);
    const int ty = tid / (BN / TN);

    float acc[TM][TN];
#pragma unroll
    for (int i = 0; i < TM; i++)
#pragma unroll
        for (int j = 0; j < TN; j++) acc[i][j] = 0.f;

    for (int k0 = 0; k0 < K; k0 += BK) {
        // --- load A tile: As[k][m], coalesced along K ---
        {
            const int ar = tid / BK;
            const int ac = tid % BK;
            const bool kin = (k0 + ac) < K;
#pragma unroll
            for (int i = 0; i < BM; i += THREADS / BK) {
                As[ac][ar + i] =
                    kin ? A[(size_t)(m0 + ar + i) * K + (k0 + ac)] : 0.f;
            }
        }
        // --- load B tile: Bs[k][n] ---
        if (BT) {
            const int bn = tid / BK;
            const int bk = tid % BK;
            const bool kin = (k0 + bk) < K;
#pragma unroll
            for (int i = 0; i < BN; i += THREADS / BK) {
                Bs[bk][bn + i] =
                    kin ? B[(size_t)(n0 + bn + i) * K + (k0 + bk)] : 0.f;
            }
        } else {
            const int br = tid / BN;
            const int bc = tid % BN;
#pragma unroll
            for (int i = 0; i < BK; i += THREADS / BN) {
                const bool kin = (k0 + br + i) < K;
                Bs[br + i][bc] =
                    kin ? B[(size_t)(k0 + br + i) * N + (n0 + bc)] : 0.f;
            }
        }
        __syncthreads();

#pragma unroll
        for (int kk = 0; kk < BK; kk++) {
            float ra[TM], rb[TN];
#pragma unroll
            for (int i = 0; i < TM; i += 4) {
                float4 v = *reinterpret_cast<const float4*>(&As[kk][ty * TM + i]);
                ra[i] = v.x; ra[i + 1] = v.y; ra[i + 2] = v.z; ra[i + 3] = v.w;
            }
#pragma unroll
            for (int j = 0; j < TN; j += 4) {
                float4 v = *reinterpret_cast<const float4*>(&Bs[kk][tx * TN + j]);
                rb[j] = v.x; rb[j + 1] = v.y; rb[j + 2] = v.z; rb[j + 3] = v.w;
            }
#pragma unroll
            for (int i = 0; i < TM; i++)
#pragma unroll
                for (int j = 0; j < TN; j++)
                    acc[i][j] = fmaf(ra[i], rb[j], acc[i][j]);
        }
        __syncthreads();
    }

    // epilogue
#pragma unroll
    for (int i = 0; i < TM; i++) {
        const int row = m0 + ty * TM + i;
#pragma unroll
        for (int j = 0; j < TN; j++) {
            const int col = n0 + tx * TN + j;
            float v = acc[i][j];
            if (bias) v += bias[col];
            if (DO_TANH) v = tanhf(v);
            Cout[(size_t)row * N + col] = v;
        }
    }
}

// ---------------------------------------------------------------------------
// Attention: per token m (B*L): alpha_w = H[m,w,:] . R[m,:] (8 dots of 768),
// softmax over w, G[m,:] = sum_w alpha_w * H[m,w,:].
// One block (256 thr = 8 warps) per token; warp w owns word w's dot product.
// ---------------------------------------------------------------------------
__global__ void __launch_bounds__(256)
attn_kernel(const float* __restrict__ H, const float* __restrict__ R,
            float* __restrict__ G)
{
    const int m    = blockIdx.x;
    const int tid  = threadIdx.x;
    const int wid  = tid >> 5;
    const int lane = tid & 31;

    __shared__ float sR[Dd];
    __shared__ float sAlpha[Wn];

    const float* Hm = H + (size_t)m * Wn * Dd;
    const float* Rm = R + (size_t)m * Dd;

    for (int d = tid; d < Dd; d += 256) sR[d] = Rm[d];
    __syncthreads();

    // warp 'wid' computes the dot for word 'wid'
    const float* Hw = Hm + wid * Dd;
    float s = 0.f;
    for (int d = lane; d < Dd; d += 32) s = fmaf(Hw[d], sR[d], s);
#pragma unroll
    for (int o = 16; o > 0; o >>= 1) s += __shfl_xor_sync(0xffffffffu, s, o);
    if (lane == 0) sAlpha[wid] = s;
    __syncthreads();

    // softmax over 8 values (computed redundantly by every thread)
    float mx = -INFINITY;
#pragma unroll
    for (int w = 0; w < Wn; w++) mx = fmaxf(mx, sAlpha[w]);
    float a[Wn];
    float den = 0.f;
#pragma unroll
    for (int w = 0; w < Wn; w++) { a[w] = expf(sAlpha[w] - mx); den += a[w]; }
    const float inv = 1.f / den;

    // weighted sum over words
    for (int d = tid; d < Dd; d += 256) {
        float g = 0.f;
#pragma unroll
        for (int w = 0; w < Wn; w++) g = fmaf(a[w], Hm[w * Dd + d], g);
        G[(size_t)m * Dd + d] = g * inv;
    }
}

// ---------------------------------------------------------------------------
// Residual + LayerNorm: out[m,:] = LN(LO[m,:] + WTD[m,:]) * gamma + beta
// One block (256 thr) per row; each thread owns 3 of the 768 elements.
// ---------------------------------------------------------------------------
__global__ void __launch_bounds__(256)
resid_ln_kernel(const float* __restrict__ LO, const float* __restrict__ WTD,
                const float* __restrict__ gamma, const float* __restrict__ beta,
                float* __restrict__ out)
{
    const int m    = blockIdx.x;
    const int tid  = threadIdx.x;
    const int wid  = tid >> 5;
    const int lane = tid & 31;

    const float* lo = LO  + (size_t)m * Dd;
    const float* wt = WTD + (size_t)m * Dd;

    float x[3];
    float s = 0.f, ss = 0.f;
#pragma unroll
    for (int i = 0; i < 3; i++) {
        const int d = tid + i * 256;
        const float v = lo[d] + wt[d];
        x[i] = v;
        s  += v;
        ss += v * v;
    }

    __shared__ float rs[8], rss[8];
#pragma unroll
    for (int o = 16; o > 0; o >>= 1) {
        s  += __shfl_xor_sync(0xffffffffu, s, o);
        ss += __shfl_xor_sync(0xffffffffu, ss, o);
    }
    if (lane == 0) { rs[wid] = s; rss[wid] = ss; }
    __syncthreads();

    s = 0.f; ss = 0.f;
#pragma unroll
    for (int w = 0; w < 8; w++) { s += rs[w]; ss += rss[w]; }

    const float mu   = s * (1.f / Dd);
    const float var  = ss * (1.f / Dd) - mu * mu;
    const float rstd = rsqrtf(var + 1e-12f);

#pragma unroll
    for (int i = 0; i < 3; i++) {
        const int d = tid + i * 256;
        out[(size_t)m * Dd + d] = (x[i] - mu) * rstd * gamma[d] + beta[d];
    }
}

// ---------------------------------------------------------------------------
// Launch. Input order per metadata:
//  0 word_embeddings [B,L,W,E]  1 layer_output [B,L,D]  2 Wt [D,E]  3 bt [D]
//  4 Ww [D,D]  5 bw [D]  6 attn_W [D,D]  7 ln_gamma [D]  8 ln_beta [D]
// ---------------------------------------------------------------------------
extern "C" void kernel_launch(void* const* d_in, const int* in_sizes, int n_in,
                              void* d_out, int out_size)
{
    (void)in_sizes; (void)n_in; (void)out_size;

    const float* WE  = (const float*)d_in[0];
    const float* LO  = (const float*)d_in[1];
    const float* Wt  = (const float*)d_in[2];
    const float* bt  = (const float*)d_in[3];
    const float* Ww  = (const float*)d_in[4];
    const float* bw  = (const float*)d_in[5];
    const float* AW  = (const float*)d_in[6];
    const float* gam = (const float*)d_in[7];
    const float* bet = (const float*)d_in[8];
    float* out = (float*)d_out;

    float *pH, *pC, *pR, *pG, *pW;
    cudaGetSymbolAddress((void**)&pH, g_H);
    cudaGetSymbolAddress((void**)&pC, g_C);
    cudaGetSymbolAddress((void**)&pR, g_R);
    cudaGetSymbolAddress((void**)&pG, g_G);
    cudaGetSymbolAddress((void**)&pW, g_WTD);

    // 1) C = attn_W @ Ww   (768x768x768, NN) — folds q@Ww into one matrix
    sgemm_kernel<64, 64, 16, 4, 4, false, false>
        <<<dim3(Dd / 64, Dd / 64), 256>>>(AW, Ww, nullptr, pC, Dd, Dd, Dd);

    // 2) H = tanh(WE @ Wt^T + bt)   (65536x768, K=200, NT)
    sgemm_kernel<128, 128, 16, 8, 8, true, true>
        <<<dim3(Dd / 128, M1 / 128), 256>>>(WE, Wt, bt, pH, M1, Dd, Ee);

    // 3) R = LO @ C   (8192x768x768, NN) — R[m] = lo[m] @ attn_W @ Ww
    sgemm_kernel<128, 128, 16, 8, 8, false, false>
        <<<dim3(Dd / 128, M2 / 128), 256>>>(LO, pC, nullptr, pR, M2, Dd, Dd);

    // 4) alpha = softmax_w(H . R); G = sum_w alpha_w * H
    attn_kernel<<<M2, 256>>>(pH, pR, pG);

    // 5) WTD = G @ Ww^T + bw   (8192x768x768, NT)
    sgemm_kernel<128, 128, 16, 8, 8, true, false>
        <<<dim3(Dd / 128, M2 / 128), 256>>>(pG, Ww, bw, pW, M2, Dd, Dd);

    // 6) out = LayerNorm(LO + WTD)
    resid_ln_kernel<<<M2, 256>>>(LO, pW, gam, bet, out);
}

// round 10
// speedup vs baseline: 1.0990x; 1.0990x over previous
#include <cuda_runtime.h>
#include <math.h>

// Problem dims (fixed by the dataset)
constexpr int Bb = 16, Ll = 512, Wn = 8, Ee = 200, Dd = 768;
constexpr int M1 = Bb * Ll * Wn;   // 65536 (B*L*W) rows for GEMM1
constexpr int M2 = Bb * Ll;        // 8192  (B*L)   rows for the rest

// Scratch (no cudaMalloc allowed) — __device__ globals.
__device__ float g_H[(size_t)M1 * Dd];   // tanh(WE @ Wt^T + bt)      [65536,768]
__device__ float g_C[Dd * Dd];           // attn_W @ Ww               [768,768]
__device__ float g_R[M2 * Dd];           // LO @ C                    [8192,768]
__device__ float g_G[M2 * Dd];           // sum_w alpha_w * H         [8192,768]
__device__ float g_WTD[M2 * Dd];         // G @ Ww^T + bw             [8192,768]

using u64 = unsigned long long;

// Packed fp32x2 FMA (Blackwell): d = a*b + d per 32-bit lane of a 64-bit pair.
// ptxas never emits FFMA2 from C++ — must come from PTX fma.rn.f32x2.
// NOTE: with "+l"(d) the accumulator is operand %0 on BOTH sides; referencing
// a nonexistent %3 ICEs nvcc (R8 failure).
__device__ __forceinline__ void ffma2(u64& d, u64 a, u64 b) {
    asm("fma.rn.f32x2 %0, %1, %2, %0;" : "+l"(d) : "l"(a), "l"(b));
}

__device__ __forceinline__ u64 pack2(float x, float y) {
    u64 r;
    asm("mov.b64 %0, {%1, %2};" : "=l"(r) : "f"(x), "f"(y));
    return r;
}
__device__ __forceinline__ void unpack2(u64 v, float& x, float& y) {
    asm("mov.b64 {%0, %1}, %2;" : "=f"(x), "=f"(y) : "l"(v));
}

// ---------------------------------------------------------------------------
// Tiled fp32 SGEMM with packed f32x2 accumulation.
//   out[m,n] = act( sum_k A[m,k] * B'(k,n) + bias[n] )
//   B'(k,n) = BT ? B[n*K + k] : B[k*N + n]
// M, N multiples of BM, BN. K may be ragged (guarded).
// ---------------------------------------------------------------------------
template <int BM, int BN, int BK, int TM, int TN, bool BT, bool DO_TANH>
__global__ void __launch_bounds__((BM / TM) * (BN / TN))
sgemm_kernel(const float* __restrict__ A, const float* __restrict__ B,
             const float* __restrict__ bias, float* __restrict__ Cout,
             int M, int N, int K)
{
    constexpr int THREADS = (BM / TM) * (BN / TN);
    constexpr int TN2 = TN / 2;
    __shared__ float As[BK][BM];
    __shared__ float Bs[BK][BN];

    const int tid = threadIdx.x;
    const int m0  = blockIdx.y * BM;
    const int n0  = blockIdx.x * BN;

    const int tx = tid % (BN / TN);
    const int ty = tid / (BN / TN);

    // f32x2 accumulators: acc2[i][j] holds columns (2j, 2j+1) of row i.
    // Bit pattern of {0.f, 0.f} is 0ull.
    u64 acc2[TM][TN2];
#pragma unroll
    for (int i = 0; i < TM; i++)
#pragma unroll
        for (int j = 0; j < TN2; j++) acc2[i][j] = 0ull;

    for (int k0 = 0; k0 < K; k0 += BK) {
        // --- load A tile: As[k][m], coalesced along K ---
        {
            const int ar = tid / BK;
            const int ac = tid % BK;
            const bool kin = (k0 + ac) < K;
#pragma unroll
            for (int i = 0; i < BM; i += THREADS / BK) {
                As[ac][ar + i] =
                    kin ? A[(size_t)(m0 + ar + i) * K + (k0 + ac)] : 0.f;
            }
        }
        // --- load B tile: Bs[k][n] ---
        if (BT) {
            const int bn = tid / BK;
            const int bk = tid % BK;
            const bool kin = (k0 + bk) < K;
#pragma unroll
            for (int i = 0; i < BN; i += THREADS / BK) {
                Bs[bk][bn + i] =
                    kin ? B[(size_t)(n0 + bn + i) * K + (k0 + bk)] : 0.f;
            }
        } else {
            const int br = tid / BN;
            const int bc = tid % BN;
#pragma unroll
            for (int i = 0; i < BK; i += THREADS / BN) {
                const bool kin = (k0 + br + i) < K;
                Bs[br + i][bc] =
                    kin ? B[(size_t)(k0 + br + i) * N + (n0 + bc)] : 0.f;
            }
        }
        __syncthreads();

#pragma unroll
        for (int kk = 0; kk < BK; kk++) {
            // A fragment (scalar), B fragment directly as f32x2 pairs.
            float ra[TM];
#pragma unroll
            for (int i = 0; i < TM; i += 4) {
                float4 v = *reinterpret_cast<const float4*>(&As[kk][ty * TM + i]);
                ra[i] = v.x; ra[i + 1] = v.y; ra[i + 2] = v.z; ra[i + 3] = v.w;
            }
            u64 rb2[TN2];
#pragma unroll
            for (int j = 0; j < TN2; j += 2) {
                ulonglong2 v = *reinterpret_cast<const ulonglong2*>(
                    &Bs[kk][tx * TN + 2 * j]);
                rb2[j] = v.x; rb2[j + 1] = v.y;
            }
#pragma unroll
            for (int i = 0; i < TM; i++) {
                const u64 a2 = pack2(ra[i], ra[i]);
#pragma unroll
                for (int j = 0; j < TN2; j++)
                    ffma2(acc2[i][j], a2, rb2[j]);
            }
        }
        __syncthreads();
    }

    // epilogue
#pragma unroll
    for (int i = 0; i < TM; i++) {
        const int row = m0 + ty * TM + i;
#pragma unroll
        for (int j = 0; j < TN2; j++) {
            const int col = n0 + tx * TN + 2 * j;
            float v0, v1;
            unpack2(acc2[i][j], v0, v1);
            if (bias) { v0 += bias[col]; v1 += bias[col + 1]; }
            if (DO_TANH) { v0 = tanhf(v0); v1 = tanhf(v1); }
            float2 o = make_float2(v0, v1);
            *reinterpret_cast<float2*>(&Cout[(size_t)row * N + col]) = o;
        }
    }
}

// ---------------------------------------------------------------------------
// Attention: per token m (B*L): alpha_w = H[m,w,:] . R[m,:] (8 dots of 768),
// softmax over w, G[m,:] = sum_w alpha_w * H[m,w,:].
// One block (256 thr = 8 warps) per token; warp w owns word w's dot product.
// ---------------------------------------------------------------------------
__global__ void __launch_bounds__(256)
attn_kernel(const float* __restrict__ H, const float* __restrict__ R,
            float* __restrict__ G)
{
    const int m    = blockIdx.x;
    const int tid  = threadIdx.x;
    const int wid  = tid >> 5;
    const int lane = tid & 31;

    __shared__ float sR[Dd];
    __shared__ float sAlpha[Wn];

    const float* Hm = H + (size_t)m * Wn * Dd;
    const float* Rm = R + (size_t)m * Dd;

    for (int d = tid; d < Dd; d += 256) sR[d] = Rm[d];
    __syncthreads();

    // warp 'wid' computes the dot for word 'wid'
    const float* Hw = Hm + wid * Dd;
    float s = 0.f;
    for (int d = lane; d < Dd; d += 32) s = fmaf(Hw[d], sR[d], s);
#pragma unroll
    for (int o = 16; o > 0; o >>= 1) s += __shfl_xor_sync(0xffffffffu, s, o);
    if (lane == 0) sAlpha[wid] = s;
    __syncthreads();

    // softmax over 8 values (computed redundantly by every thread)
    float mx = -INFINITY;
#pragma unroll
    for (int w = 0; w < Wn; w++) mx = fmaxf(mx, sAlpha[w]);
    float a[Wn];
    float den = 0.f;
#pragma unroll
    for (int w = 0; w < Wn; w++) { a[w] = expf(sAlpha[w] - mx); den += a[w]; }
    const float inv = 1.f / den;

    // weighted sum over words
    for (int d = tid; d < Dd; d += 256) {
        float g = 0.f;
#pragma unroll
        for (int w = 0; w < Wn; w++) g = fmaf(a[w], Hm[w * Dd + d], g);
        G[(size_t)m * Dd + d] = g * inv;
    }
}

// ---------------------------------------------------------------------------
// Residual + LayerNorm: out[m,:] = LN(LO[m,:] + WTD[m,:]) * gamma + beta
// ---------------------------------------------------------------------------
__global__ void __launch_bounds__(256)
resid_ln_kernel(const float* __restrict__ LO, const float* __restrict__ WTD,
                const float* __restrict__ gamma, const float* __restrict__ beta,
                float* __restrict__ out)
{
    const int m    = blockIdx.x;
    const int tid  = threadIdx.x;
    const int wid  = tid >> 5;
    const int lane = tid & 31;

    const float* lo = LO  + (size_t)m * Dd;
    const float* wt = WTD + (size_t)m * Dd;

    float x[3];
    float s = 0.f, ss = 0.f;
#pragma unroll
    for (int i = 0; i < 3; i++) {
        const int d = tid + i * 256;
        const float v = lo[d] + wt[d];
        x[i] = v;
        s  += v;
        ss += v * v;
    }

    __shared__ float rs[8], rss[8];
#pragma unroll
    for (int o = 16; o > 0; o >>= 1) {
        s  += __shfl_xor_sync(0xffffffffu, s, o);
        ss += __shfl_xor_sync(0xffffffffu, ss, o);
    }
    if (lane == 0) { rs[wid] = s; rss[wid] = ss; }
    __syncthreads();

    s = 0.f; ss = 0.f;
#pragma unroll
    for (int w = 0; w < 8; w++) { s += rs[w]; ss += rss[w]; }

    const float mu   = s * (1.f / Dd);
    const float var  = ss * (1.f / Dd) - mu * mu;
    const float rstd = rsqrtf(var + 1e-12f);

#pragma unroll
    for (int i = 0; i < 3; i++) {
        const int d = tid + i * 256;
        out[(size_t)m * Dd + d] = (x[i] - mu) * rstd * gamma[d] + beta[d];
    }
}

// ---------------------------------------------------------------------------
// Launch. Input order per metadata:
//  0 word_embeddings [B,L,W,E]  1 layer_output [B,L,D]  2 Wt [D,E]  3 bt [D]
//  4 Ww [D,D]  5 bw [D]  6 attn_W [D,D]  7 ln_gamma [D]  8 ln_beta [D]
// ---------------------------------------------------------------------------
extern "C" void kernel_launch(void* const* d_in, const int* in_sizes, int n_in,
                              void* d_out, int out_size)
{
    (void)in_sizes; (void)n_in; (void)out_size;

    const float* WE  = (const float*)d_in[0];
    const float* LO  = (const float*)d_in[1];
    const float* Wt  = (const float*)d_in[2];
    const float* bt  = (const float*)d_in[3];
    const float* Ww  = (const float*)d_in[4];
    const float* bw  = (const float*)d_in[5];
    const float* AW  = (const float*)d_in[6];
    const float* gam = (const float*)d_in[7];
    const float* bet = (const float*)d_in[8];
    float* out = (float*)d_out;

    float *pH, *pC, *pR, *pG, *pW;
    cudaGetSymbolAddress((void**)&pH, g_H);
    cudaGetSymbolAddress((void**)&pC, g_C);
    cudaGetSymbolAddress((void**)&pR, g_R);
    cudaGetSymbolAddress((void**)&pG, g_G);
    cudaGetSymbolAddress((void**)&pW, g_WTD);

    // 1) C = attn_W @ Ww   (768x768x768, NN) — folds q@Ww into one matrix
    sgemm_kernel<64, 64, 16, 4, 4, false, false>
        <<<dim3(Dd / 64, Dd / 64), 256>>>(AW, Ww, nullptr, pC, Dd, Dd, Dd);

    // 2) H = tanh(WE @ Wt^T + bt)   (65536x768, K=200, NT)
    sgemm_kernel<128, 128, 16, 8, 8, true, true>
        <<<dim3(Dd / 128, M1 / 128), 256>>>(WE, Wt, bt, pH, M1, Dd, Ee);

    // 3) R = LO @ C   (8192x768x768, NN) — R[m] = lo[m] @ attn_W @ Ww
    sgemm_kernel<128, 128, 16, 8, 8, false, false>
        <<<dim3(Dd / 128, M2 / 128), 256>>>(LO, pC, nullptr, pR, M2, Dd, Dd);

    // 4) alpha = softmax_w(H . R); G = sum_w alpha_w * H
    attn_kernel<<<M2, 256>>>(pH, pR, pG);

    // 5) WTD = G @ Ww^T + bw   (8192x768x768, NT)
    sgemm_kernel<128, 128, 16, 8, 8, true, false>
        <<<dim3(Dd / 128, M2 / 128), 256>>>(pG, Ww, bw, pW, M2, Dd, Dd);

    // 6) out = LayerNorm(LO + WTD)
    resid_ln_kernel<<<M2, 256>>>(LO, pW, gam, bet, out);
}

// round 12
// speedup vs baseline: 2.3776x; 2.1635x over previous
#include <cuda_runtime.h>
#include <cuda_bf16.h>
#include <math.h>
#include <stdint.h>

// Problem dims (fixed by the dataset)
constexpr int Wn = 8, Ee = 200, Dd = 768;
constexpr int M1 = 65536;          // B*L*W rows for GEMM H
constexpr int M2 = 8192;           // B*L rows
constexpr int KP1 = 224;           // K pad for E=200 (multiple of 32)
constexpr int KX1 = 3 * KP1;       // 672  = split-K' for GEMM H
constexpr int KP2 = 768;
constexpr int KX2 = 3 * KP2;       // 2304 = split-K' for GEMM R / WTD

// ---- scratch (__device__ globals; no cudaMalloc allowed) ----
__device__ float g_H[(size_t)M1 * Dd];
__device__ float g_C[Dd * Dd];
__device__ float g_R[M2 * Dd];
__device__ float g_G[M2 * Dd];
__device__ float g_WTD[M2 * Dd];
__device__ __align__(16) __nv_bfloat16 gA1[(size_t)M1 * KX1];  // WE split
__device__ __align__(16) __nv_bfloat16 gB1[(size_t)Dd * KX1];  // Wt split
__device__ __align__(16) __nv_bfloat16 gA2[(size_t)M2 * KX2];  // LO / G split
__device__ __align__(16) __nv_bfloat16 gB2[(size_t)Dd * KX2];  // (AW@Ww)^T split
__device__ __align__(16) __nv_bfloat16 gB3[(size_t)Dd * KX2];  // Ww split

using u64 = unsigned long long;

// ===================== PTX helpers (compute_103-safe: sm_80+ subset) ========
__device__ __forceinline__ uint32_t smem_u32(const void* p) {
    uint32_t a;
    asm("{ .reg .u64 t; cvta.to.shared.u64 t, %1; cvt.u32.u64 %0, t; }"
        : "=r"(a) : "l"(p));
    return a;
}
__device__ __forceinline__ void cp16(uint32_t dst, const void* src) {
    asm volatile("cp.async.cg.shared.global [%0], [%1], 16;"
                 :: "r"(dst), "l"(src));
}
#define CP_COMMIT() asm volatile("cp.async.commit_group;" ::: "memory")
template <int N>
__device__ __forceinline__ void cp_wait() {
    asm volatile("cp.async.wait_group %0;" :: "n"(N) : "memory");
}
__device__ __forceinline__ void ldsm4(uint32_t& r0, uint32_t& r1,
                                      uint32_t& r2, uint32_t& r3, uint32_t a) {
    asm volatile("ldmatrix.sync.aligned.m8n8.x4.shared.b16 {%0,%1,%2,%3}, [%4];"
                 : "=r"(r0), "=r"(r1), "=r"(r2), "=r"(r3) : "r"(a));
}
__device__ __forceinline__ void mma_bf16(float* acc, const uint32_t* a,
                                         const uint32_t* b) {
    asm volatile(
        "mma.sync.aligned.m16n8k16.row.col.f32.bf16.bf16.f32 "
        "{%0,%1,%2,%3}, {%4,%5,%6,%7}, {%8,%9}, {%0,%1,%2,%3};"
        : "+f"(acc[0]), "+f"(acc[1]), "+f"(acc[2]), "+f"(acc[3])
        : "r"(a[0]), "r"(a[1]), "r"(a[2]), "r"(a[3]), "r"(b[0]), "r"(b[1]));
}

// ===================== Tensor-core GEMM (HMMA, NT) ==========================
// Out[m,n] = act( sum_k A[m,k]*B[n,k] + bias[n] ), A [M,Kp], B [N,Kp] bf16.
// Block tile 128x128x32, 8 warps (2m x 4n, 64x32 each), 2-stage cp.async.
constexpr int SS = 40;   // SMEM row stride in bf16 (32 + 8 pad; 80B, 16B-aligned)

template <bool DO_TANH>
__global__ void __launch_bounds__(256, 2)
hgemm_kernel(const __nv_bfloat16* __restrict__ A, const __nv_bfloat16* __restrict__ B,
             const float* __restrict__ bias, float* __restrict__ Out,
             int Kp, int Nglob)
{
    __shared__ __align__(16) __nv_bfloat16 sA[2][128 * SS];
    __shared__ __align__(16) __nv_bfloat16 sB[2][128 * SS];

    const int tid = threadIdx.x, wid = tid >> 5, lane = tid & 31;
    const int wm = wid >> 2, wn = wid & 3;             // 2 x 4 warp grid
    const int m0 = blockIdx.y * 128, n0 = blockIdx.x * 128;
    const int NC = Kp / 32;

    const uint32_t aBase[2] = {smem_u32(&sA[0][0]), smem_u32(&sA[1][0])};
    const uint32_t bBase[2] = {smem_u32(&sB[0][0]), smem_u32(&sB[1][0])};

    // global->smem loader: 512 x 16B per operand tile; 2 per thread each
    const int lr = tid >> 2;           // row 0..63 step: two iters cover 128
    const int lc = tid & 3;            // 16B column chunk 0..3
    auto load_tile = [&](int s, int kc) {
        const __nv_bfloat16* ag =
            A + (size_t)(m0 + lr) * Kp + kc * 32 + lc * 8;
        const __nv_bfloat16* bg =
            B + (size_t)(n0 + lr) * Kp + kc * 32 + lc * 8;
        const uint32_t doff = (uint32_t)(lr * SS + lc * 8) * 2;
        cp16(aBase[s] + doff, ag);
        cp16(aBase[s] + doff + 64 * SS * 2, ag + (size_t)64 * Kp);
        cp16(bBase[s] + doff, bg);
        cp16(bBase[s] + doff + 64 * SS * 2, bg + (size_t)64 * Kp);
    };

    float acc[4][4][4];
#pragma unroll
    for (int f = 0; f < 4; f++)
#pragma unroll
        for (int g = 0; g < 4; g++)
#pragma unroll
            for (int x = 0; x < 4; x++) acc[f][g][x] = 0.f;

    // ldmatrix address components (within a stage, in bytes)
    // A: row = wm*64 + f*16 + (lane&15), col = kk*16 + ((lane>>1)&8)
    const uint32_t aRow = (uint32_t)(wm * 64 + (lane & 15)) * SS * 2;
    const uint32_t aKof = (uint32_t)((lane >> 1) & 8) * 2;
    // B: n = wn*32 + p*16 + ((lane>>4)<<3) + (lane&7), k = kk*16 + (lane&8)
    const uint32_t bRow =
        (uint32_t)(wn * 32 + ((lane >> 4) << 3) + (lane & 7)) * SS * 2;
    const uint32_t bKof = (uint32_t)(lane & 8) * 2;

    load_tile(0, 0);
    CP_COMMIT();

    for (int c = 0; c < NC; c++) {
        const int s = c & 1;
        if (c + 1 < NC) {
            load_tile(s ^ 1, c + 1);
            CP_COMMIT();
            cp_wait<1>();
        } else {
            cp_wait<0>();
        }
        __syncthreads();

#pragma unroll
        for (int kk = 0; kk < 2; kk++) {
            uint32_t af[4][4];
#pragma unroll
            for (int f = 0; f < 4; f++) {
                uint32_t addr = aBase[s] + aRow + (uint32_t)(f * 16) * SS * 2 +
                                (uint32_t)(kk * 16) * 2 + aKof;
                ldsm4(af[f][0], af[f][1], af[f][2], af[f][3], addr);
            }
            uint32_t bf[4][2];
#pragma unroll
            for (int p = 0; p < 2; p++) {
                uint32_t addr = bBase[s] + bRow + (uint32_t)(p * 16) * SS * 2 +
                                (uint32_t)(kk * 16) * 2 + bKof;
                ldsm4(bf[2 * p][0], bf[2 * p][1], bf[2 * p + 1][0],
                      bf[2 * p + 1][1], addr);
            }
#pragma unroll
            for (int f = 0; f < 4; f++)
#pragma unroll
                for (int g = 0; g < 4; g++)
                    mma_bf16(acc[f][g], af[f], bf[g]);
        }
        __syncthreads();
    }

    // epilogue: c-frag m16n8 layout -> rows t/4, t/4+8; cols 2(t%4), +1
#pragma unroll
    for (int f = 0; f < 4; f++) {
        const int row0 = m0 + wm * 64 + f * 16 + (lane >> 2);
#pragma unroll
        for (int g = 0; g < 4; g++) {
            const int col = n0 + wn * 32 + g * 8 + 2 * (lane & 3);
            float v0 = acc[f][g][0], v1 = acc[f][g][1];
            float v2 = acc[f][g][2], v3 = acc[f][g][3];
            if (bias) {
                const float b0 = bias[col], b1 = bias[col + 1];
                v0 += b0; v1 += b1; v2 += b0; v3 += b1;
            }
            if (DO_TANH) {
                v0 = tanhf(v0); v1 = tanhf(v1);
                v2 = tanhf(v2); v3 = tanhf(v3);
            }
            *reinterpret_cast<float2*>(&Out[(size_t)row0 * Nglob + col]) =
                make_float2(v0, v1);
            *reinterpret_cast<float2*>(&Out[(size_t)(row0 + 8) * Nglob + col]) =
                make_float2(v2, v3);
        }
    }
}

// ===================== split-to-bf16 hi/lo (K-concatenated) =================
// dst row m = [hi | hi | lo] (A side) or [hi | lo | hi] (B side); blocks Kpad.
template <bool BSIDE, bool TRANS>
__global__ void split_kernel(const float* __restrict__ src,
                             __nv_bfloat16* __restrict__ dst,
                             int Msz, int Ksrc, int Kpad)
{
    int idx = blockIdx.x * 256 + threadIdx.x;
    if (idx >= Msz * Kpad) return;
    int m = idx / Kpad, k = idx % Kpad;
    float x = 0.f;
    if (k < Ksrc)
        x = TRANS ? src[(size_t)k * Msz + m] : src[(size_t)m * Ksrc + k];
    __nv_bfloat16 hi = __float2bfloat16(x);
    __nv_bfloat16 lo = __float2bfloat16(x - __bfloat162float(hi));
    size_t base = (size_t)m * 3 * Kpad;
    dst[base + k]            = hi;
    dst[base + Kpad + k]     = BSIDE ? lo : hi;
    dst[base + 2 * Kpad + k] = BSIDE ? hi : lo;
}

// ===================== fp32 SGEMM (tiny 768^3: C = attn_W @ Ww) =============
__device__ __forceinline__ void ffma2(u64& d, u64 a, u64 b) {
    asm("fma.rn.f32x2 %0, %1, %2, %0;" : "+l"(d) : "l"(a), "l"(b));
}
__device__ __forceinline__ u64 pack2f(float x, float y) {
    u64 r; asm("mov.b64 %0, {%1, %2};" : "=l"(r) : "f"(x), "f"(y)); return r;
}
__device__ __forceinline__ void unpack2f(u64 v, float& x, float& y) {
    asm("mov.b64 {%0, %1}, %2;" : "=f"(x), "=f"(y) : "l"(v));
}

__global__ void __launch_bounds__(256)
sgemm64_kernel(const float* __restrict__ A, const float* __restrict__ B,
               float* __restrict__ Cout, int N, int K)
{
    constexpr int BM = 64, BN = 64, BK = 16, TM = 4, TN = 4, TN2 = 2;
    __shared__ float As[BK][BM];
    __shared__ float Bs[BK][BN];
    const int tid = threadIdx.x;
    const int m0 = blockIdx.y * BM, n0 = blockIdx.x * BN;
    const int tx = tid % (BN / TN), ty = tid / (BN / TN);

    u64 acc2[TM][TN2];
#pragma unroll
    for (int i = 0; i < TM; i++)
#pragma unroll
        for (int j = 0; j < TN2; j++) acc2[i][j] = 0ull;

    for (int k0 = 0; k0 < K; k0 += BK) {
        {
            const int ar = tid / BK, ac = tid % BK;
#pragma unroll
            for (int i = 0; i < BM; i += 256 / BK)
                As[ac][ar + i] = A[(size_t)(m0 + ar + i) * K + (k0 + ac)];
        }
        {
            const int br = tid / BN, bc = tid % BN;
#pragma unroll
            for (int i = 0; i < BK; i += 256 / BN)
                Bs[br + i][bc] = B[(size_t)(k0 + br + i) * N + (n0 + bc)];
        }
        __syncthreads();
#pragma unroll
        for (int kk = 0; kk < BK; kk++) {
            float ra[TM];
            float4 va = *reinterpret_cast<const float4*>(&As[kk][ty * TM]);
            ra[0] = va.x; ra[1] = va.y; ra[2] = va.z; ra[3] = va.w;
            ulonglong2 vb = *reinterpret_cast<const ulonglong2*>(&Bs[kk][tx * TN]);
            u64 rb2[TN2] = {vb.x, vb.y};
#pragma unroll
            for (int i = 0; i < TM; i++) {
                const u64 a2 = pack2f(ra[i], ra[i]);
#pragma unroll
                for (int j = 0; j < TN2; j++) ffma2(acc2[i][j], a2, rb2[j]);
            }
        }
        __syncthreads();
    }
#pragma unroll
    for (int i = 0; i < TM; i++) {
        const int row = m0 + ty * TM + i;
#pragma unroll
        for (int j = 0; j < TN2; j++) {
            float v0, v1;
            unpack2f(acc2[i][j], v0, v1);
            const int col = n0 + tx * TN + 2 * j;
            *reinterpret_cast<float2*>(&Cout[(size_t)row * N + col]) =
                make_float2(v0, v1);
        }
    }
}

// ===================== attention (H cached in SMEM) =========================
__global__ void __launch_bounds__(256)
attn_kernel(const float* __restrict__ H, const float* __restrict__ R,
            float* __restrict__ G)
{
    const int m = blockIdx.x, tid = threadIdx.x;
    const int wid = tid >> 5, lane = tid & 31;

    __shared__ float sH[Wn * Dd];
    __shared__ float sR[Dd];
    __shared__ float sAlpha[Wn];

    const float* Hm = H + (size_t)m * Wn * Dd;
    const float* Rm = R + (size_t)m * Dd;

    for (int i = tid; i < Wn * Dd; i += 256) sH[i] = Hm[i];
    for (int d = tid; d < Dd; d += 256) sR[d] = Rm[d];
    __syncthreads();

    const float* Hw = sH + wid * Dd;
    float s = 0.f;
    for (int d = lane; d < Dd; d += 32) s = fmaf(Hw[d], sR[d], s);
#pragma unroll
    for (int o = 16; o > 0; o >>= 1) s += __shfl_xor_sync(0xffffffffu, s, o);
    if (lane == 0) sAlpha[wid] = s;
    __syncthreads();

    float mx = -INFINITY;
#pragma unroll
    for (int w = 0; w < Wn; w++) mx = fmaxf(mx, sAlpha[w]);
    float a[Wn], den = 0.f;
#pragma unroll
    for (int w = 0; w < Wn; w++) { a[w] = expf(sAlpha[w] - mx); den += a[w]; }
    const float inv = 1.f / den;

    for (int d = tid; d < Dd; d += 256) {
        float g = 0.f;
#pragma unroll
        for (int w = 0; w < Wn; w++) g = fmaf(a[w], sH[w * Dd + d], g);
        G[(size_t)m * Dd + d] = g * inv;
    }
}

// ===================== residual + LayerNorm =================================
__global__ void __launch_bounds__(256)
resid_ln_kernel(const float* __restrict__ LO, const float* __restrict__ WTD,
                const float* __restrict__ gamma, const float* __restrict__ beta,
                float* __restrict__ out)
{
    const int m = blockIdx.x, tid = threadIdx.x;
    const int wid = tid >> 5, lane = tid & 31;
    const float* lo = LO + (size_t)m * Dd;
    const float* wt = WTD + (size_t)m * Dd;

    float x[3], s = 0.f, ss = 0.f;
#pragma unroll
    for (int i = 0; i < 3; i++) {
        const int d = tid + i * 256;
        const float v = lo[d] + wt[d];
        x[i] = v; s += v; ss += v * v;
    }
    __shared__ float rs[8], rss[8];
#pragma unroll
    for (int o = 16; o > 0; o >>= 1) {
        s  += __shfl_xor_sync(0xffffffffu, s, o);
        ss += __shfl_xor_sync(0xffffffffu, ss, o);
    }
    if (lane == 0) { rs[wid] = s; rss[wid] = ss; }
    __syncthreads();
    s = 0.f; ss = 0.f;
#pragma unroll
    for (int w = 0; w < 8; w++) { s += rs[w]; ss += rss[w]; }
    const float mu = s * (1.f / Dd);
    const float var = ss * (1.f / Dd) - mu * mu;
    const float rstd = rsqrtf(var + 1e-12f);
#pragma unroll
    for (int i = 0; i < 3; i++) {
        const int d = tid + i * 256;
        out[(size_t)m * Dd + d] = (x[i] - mu) * rstd * gamma[d] + beta[d];
    }
}

// ===================== launch ===============================================
extern "C" void kernel_launch(void* const* d_in, const int* in_sizes, int n_in,
                              void* d_out, int out_size)
{
    (void)in_sizes; (void)n_in; (void)out_size;
    const float* WE  = (const float*)d_in[0];
    const float* LO  = (const float*)d_in[1];
    const float* Wt  = (const float*)d_in[2];
    const float* bt  = (const float*)d_in[3];
    const float* Ww  = (const float*)d_in[4];
    const float* bw  = (const float*)d_in[5];
    const float* AW  = (const float*)d_in[6];
    const float* gam = (const float*)d_in[7];
    const float* bet = (const float*)d_in[8];
    float* out = (float*)d_out;

    float *pH, *pC, *pR, *pG, *pW;
    __nv_bfloat16 *pA1, *pB1, *pA2, *pB2, *pB3;
    cudaGetSymbolAddress((void**)&pH, g_H);
    cudaGetSymbolAddress((void**)&pC, g_C);
    cudaGetSymbolAddress((void**)&pR, g_R);
    cudaGetSymbolAddress((void**)&pG, g_G);
    cudaGetSymbolAddress((void**)&pW, g_WTD);
    cudaGetSymbolAddress((void**)&pA1, gA1);
    cudaGetSymbolAddress((void**)&pB1, gB1);
    cudaGetSymbolAddress((void**)&pA2, gA2);
    cudaGetSymbolAddress((void**)&pB2, gB2);
    cudaGetSymbolAddress((void**)&pB3, gB3);

    // splits (independent of each other)
    split_kernel<false, false><<<(M1 * KP1 + 255) / 256, 256>>>(WE, pA1, M1, Ee, KP1);
    split_kernel<true,  false><<<(Dd * KP1 + 255) / 256, 256>>>(Wt, pB1, Dd, Ee, KP1);
    split_kernel<false, false><<<(M2 * KP2 + 255) / 256, 256>>>(LO, pA2, M2, Dd, KP2);
    split_kernel<true,  false><<<(Dd * KP2 + 255) / 256, 256>>>(Ww, pB3, Dd, Dd, KP2);

    // C = attn_W @ Ww (fp32), then split C^T for the NT tensor GEMM
    sgemm64_kernel<<<dim3(Dd / 64, Dd / 64), 256>>>(AW, Ww, pC, Dd, Dd);
    split_kernel<true, true><<<(Dd * KP2 + 255) / 256, 256>>>(pC, pB2, Dd, Dd, KP2);

    // H = tanh(WE @ Wt^T + bt)   [65536 x 768], K'=672
    hgemm_kernel<true><<<dim3(Dd / 128, M1 / 128), 256>>>(pA1, pB1, bt, pH, KX1, Dd);

    // R = LO @ (attn_W@Ww)       [8192 x 768], K'=2304
    hgemm_kernel<false><<<dim3(Dd / 128, M2 / 128), 256>>>(pA2, pB2, nullptr, pR, KX2, Dd);

    // softmax attention -> G
    attn_kernel<<<M2, 256>>>(pH, pR, pG);

    // split G, then WTD = G @ Ww^T + bw
    split_kernel<false, false><<<(M2 * KP2 + 255) / 256, 256>>>(pG, pA2, M2, Dd, KP2);
    hgemm_kernel<false><<<dim3(Dd / 128, M2 / 128), 256>>>(pA2, pB3, bw, pW, KX2, Dd);

    // out = LayerNorm(LO + WTD)
    resid_ln_kernel<<<M2, 256>>>(LO, pW, gam, bet, out);
}

// round 13
// speedup vs baseline: 2.4927x; 1.0484x over previous
#include <cuda_runtime.h>
#include <cuda_bf16.h>
#include <math.h>
#include <stdint.h>

// Problem dims (fixed by the dataset)
constexpr int Wn = 8, Ee = 200, Dd = 768;
constexpr int M1 = 65536;          // B*L*W rows for GEMM H
constexpr int M2 = 8192;           // B*L rows
constexpr int KP1 = 224;           // K pad for E=200 (multiple of 32)
constexpr int KX1 = 3 * KP1;       // 672  = split-K' for GEMM H
constexpr int KP2 = 768;
constexpr int KX2 = 3 * KP2;       // 2304 = split-K' for GEMM R / WTD

// ---- scratch (__device__ globals; no cudaMalloc allowed) ----
__device__ float g_H[(size_t)M1 * Dd];
__device__ float g_C[Dd * Dd];
__device__ float g_R[M2 * Dd];
__device__ float g_WTD[M2 * Dd];
__device__ __align__(16) __nv_bfloat16 gA1[(size_t)M1 * KX1];  // WE split
__device__ __align__(16) __nv_bfloat16 gB1[(size_t)Dd * KX1];  // Wt split
__device__ __align__(16) __nv_bfloat16 gA2[(size_t)M2 * KX2];  // LO split, then G split
__device__ __align__(16) __nv_bfloat16 gB2[(size_t)Dd * KX2];  // (AW@Ww)^T split
__device__ __align__(16) __nv_bfloat16 gB3[(size_t)Dd * KX2];  // Ww split

using u64 = unsigned long long;

// ===================== PTX helpers (compute_103-safe: sm_80+ subset) ========
__device__ __forceinline__ uint32_t smem_u32(const void* p) {
    uint32_t a;
    asm("{ .reg .u64 t; cvta.to.shared.u64 t, %1; cvt.u32.u64 %0, t; }"
        : "=r"(a) : "l"(p));
    return a;
}
__device__ __forceinline__ void cp16(uint32_t dst, const void* src) {
    asm volatile("cp.async.cg.shared.global [%0], [%1], 16;"
                 :: "r"(dst), "l"(src));
}
#define CP_COMMIT() asm volatile("cp.async.commit_group;" ::: "memory")
template <int N>
__device__ __forceinline__ void cp_wait() {
    asm volatile("cp.async.wait_group %0;" :: "n"(N) : "memory");
}
__device__ __forceinline__ void ldsm4(uint32_t& r0, uint32_t& r1,
                                      uint32_t& r2, uint32_t& r3, uint32_t a) {
    asm volatile("ldmatrix.sync.aligned.m8n8.x4.shared.b16 {%0,%1,%2,%3}, [%4];"
                 : "=r"(r0), "=r"(r1), "=r"(r2), "=r"(r3) : "r"(a));
}
__device__ __forceinline__ void mma_bf16(float* acc, const uint32_t* a,
                                         const uint32_t* b) {
    asm volatile(
        "mma.sync.aligned.m16n8k16.row.col.f32.bf16.bf16.f32 "
        "{%0,%1,%2,%3}, {%4,%5,%6,%7}, {%8,%9}, {%0,%1,%2,%3};"
        : "+f"(acc[0]), "+f"(acc[1]), "+f"(acc[2]), "+f"(acc[3])
        : "r"(a[0]), "r"(a[1]), "r"(a[2]), "r"(a[3]), "r"(b[0]), "r"(b[1]));
}

// ===================== Tensor-core GEMM (HMMA, NT, 3-stage) =================
// Out[m,n] = act( sum_k A[m,k]*B[n,k] + bias[n] ), A [M,Kp], B [N,Kp] bf16.
// Block tile 128x128x32, 8 warps (2m x 4n, 64x32 each), 3-stage cp.async.
constexpr int SS = 40;        // SMEM row stride in bf16 (32 + 8 pad; 80B)
constexpr int STAGES = 3;
constexpr int OPBYTES = 128 * SS * 2;                 // one operand tile
constexpr int HG_SMEM = 2 * STAGES * OPBYTES;         // 61440 B

template <bool DO_TANH>
__global__ void __launch_bounds__(256, 2)
hgemm_kernel(const __nv_bfloat16* __restrict__ A, const __nv_bfloat16* __restrict__ B,
             const float* __restrict__ bias, float* __restrict__ Out,
             int Kp, int Nglob)
{
    extern __shared__ __align__(16) char dynsmem[];
    __nv_bfloat16* sA = reinterpret_cast<__nv_bfloat16*>(dynsmem);
    __nv_bfloat16* sB = sA + STAGES * 128 * SS;

    const int tid = threadIdx.x, wid = tid >> 5, lane = tid & 31;
    const int wm = wid >> 2, wn = wid & 3;             // 2 x 4 warp grid
    const int m0 = blockIdx.y * 128, n0 = blockIdx.x * 128;
    const int NC = Kp / 32;

    uint32_t aBase[STAGES], bBase[STAGES];
#pragma unroll
    for (int s = 0; s < STAGES; s++) {
        aBase[s] = smem_u32(sA + s * 128 * SS);
        bBase[s] = smem_u32(sB + s * 128 * SS);
    }

    // global->smem loader: 512 x 16B per operand tile; 2 per thread each
    const int lr = tid >> 2;           // row 0..63; two iters cover 128
    const int lc = tid & 3;            // 16B column chunk 0..3
    const uint32_t doff = (uint32_t)(lr * SS + lc * 8) * 2;
    auto load_tile = [&](int s, int kc) {
        const __nv_bfloat16* ag = A + (size_t)(m0 + lr) * Kp + kc * 32 + lc * 8;
        const __nv_bfloat16* bg = B + (size_t)(n0 + lr) * Kp + kc * 32 + lc * 8;
        cp16(aBase[s] + doff, ag);
        cp16(aBase[s] + doff + 64 * SS * 2, ag + (size_t)64 * Kp);
        cp16(bBase[s] + doff, bg);
        cp16(bBase[s] + doff + 64 * SS * 2, bg + (size_t)64 * Kp);
    };

    float acc[4][4][4];
#pragma unroll
    for (int f = 0; f < 4; f++)
#pragma unroll
        for (int g = 0; g < 4; g++)
#pragma unroll
            for (int x = 0; x < 4; x++) acc[f][g][x] = 0.f;

    // ldmatrix address components (within a stage, in bytes)
    const uint32_t aRow = (uint32_t)(wm * 64 + (lane & 15)) * SS * 2;
    const uint32_t aKof = (uint32_t)((lane >> 1) & 8) * 2;
    const uint32_t bRow =
        (uint32_t)(wn * 32 + ((lane >> 4) << 3) + (lane & 7)) * SS * 2;
    const uint32_t bKof = (uint32_t)(lane & 8) * 2;

    load_tile(0, 0); CP_COMMIT();
    load_tile(1, 1); CP_COMMIT();

    int buf = 0;
    for (int c = 0; c < NC; c++) {
        if (c + 1 < NC) cp_wait<1>(); else cp_wait<0>();
        __syncthreads();                 // all warps done with buf being reloaded
        if (c + 2 < NC) { load_tile((buf + 2) % STAGES, c + 2); CP_COMMIT(); }

#pragma unroll
        for (int kk = 0; kk < 2; kk++) {
            uint32_t af[4][4];
#pragma unroll
            for (int f = 0; f < 4; f++) {
                uint32_t addr = aBase[buf] + aRow + (uint32_t)(f * 16) * SS * 2 +
                                (uint32_t)(kk * 16) * 2 + aKof;
                ldsm4(af[f][0], af[f][1], af[f][2], af[f][3], addr);
            }
            uint32_t bf[4][2];
#pragma unroll
            for (int p = 0; p < 2; p++) {
                uint32_t addr = bBase[buf] + bRow + (uint32_t)(p * 16) * SS * 2 +
                                (uint32_t)(kk * 16) * 2 + bKof;
                ldsm4(bf[2 * p][0], bf[2 * p][1], bf[2 * p + 1][0],
                      bf[2 * p + 1][1], addr);
            }
#pragma unroll
            for (int f = 0; f < 4; f++)
#pragma unroll
                for (int g = 0; g < 4; g++)
                    mma_bf16(acc[f][g], af[f], bf[g]);
        }
        buf = (buf + 1) % STAGES;
    }

    // epilogue: c-frag m16n8 -> rows t/4, t/4+8; cols 2(t%4), +1
#pragma unroll
    for (int f = 0; f < 4; f++) {
        const int row0 = m0 + wm * 64 + f * 16 + (lane >> 2);
#pragma unroll
        for (int g = 0; g < 4; g++) {
            const int col = n0 + wn * 32 + g * 8 + 2 * (lane & 3);
            float v0 = acc[f][g][0], v1 = acc[f][g][1];
            float v2 = acc[f][g][2], v3 = acc[f][g][3];
            if (bias) {
                const float b0 = bias[col], b1 = bias[col + 1];
                v0 += b0; v1 += b1; v2 += b0; v3 += b1;
            }
            if (DO_TANH) {
                v0 = tanhf(v0); v1 = tanhf(v1);
                v2 = tanhf(v2); v3 = tanhf(v3);
            }
            *reinterpret_cast<float2*>(&Out[(size_t)row0 * Nglob + col]) =
                make_float2(v0, v1);
            *reinterpret_cast<float2*>(&Out[(size_t)(row0 + 8) * Nglob + col]) =
                make_float2(v2, v3);
        }
    }
}

// ===================== split-to-bf16 hi/lo (K-concatenated) =================
// dst row m = [hi | hi | lo] (A side) or [hi | lo | hi] (B side); blocks Kpad.
template <bool BSIDE, bool TRANS>
__global__ void split_kernel(const float* __restrict__ src,
                             __nv_bfloat16* __restrict__ dst,
                             int Msz, int Ksrc, int Kpad)
{
    int idx = blockIdx.x * 256 + threadIdx.x;
    if (idx >= Msz * Kpad) return;
    int m = idx / Kpad, k = idx % Kpad;
    float x = 0.f;
    if (k < Ksrc)
        x = TRANS ? src[(size_t)k * Msz + m] : src[(size_t)m * Ksrc + k];
    __nv_bfloat16 hi = __float2bfloat16(x);
    __nv_bfloat16 lo = __float2bfloat16(x - __bfloat162float(hi));
    size_t base = (size_t)m * 3 * Kpad;
    dst[base + k]            = hi;
    dst[base + Kpad + k]     = BSIDE ? lo : hi;
    dst[base + 2 * Kpad + k] = BSIDE ? hi : lo;
}

// ===================== fp32 SGEMM (tiny 768^3: C = attn_W @ Ww) =============
__device__ __forceinline__ void ffma2(u64& d, u64 a, u64 b) {
    asm("fma.rn.f32x2 %0, %1, %2, %0;" : "+l"(d) : "l"(a), "l"(b));
}
__device__ __forceinline__ u64 pack2f(float x, float y) {
    u64 r; asm("mov.b64 %0, {%1, %2};" : "=l"(r) : "f"(x), "f"(y)); return r;
}
__device__ __forceinline__ void unpack2f(u64 v, float& x, float& y) {
    asm("mov.b64 {%0, %1}, %2;" : "=f"(x), "=f"(y) : "l"(v));
}

__global__ void __launch_bounds__(256)
sgemm64_kernel(const float* __restrict__ A, const float* __restrict__ B,
               float* __restrict__ Cout, int N, int K)
{
    constexpr int BM = 64, BN = 64, BK = 16, TM = 4, TN = 4, TN2 = 2;
    __shared__ float As[BK][BM];
    __shared__ float Bs[BK][BN];
    const int tid = threadIdx.x;
    const int m0 = blockIdx.y * BM, n0 = blockIdx.x * BN;
    const int tx = tid % (BN / TN), ty = tid / (BN / TN);

    u64 acc2[TM][TN2];
#pragma unroll
    for (int i = 0; i < TM; i++)
#pragma unroll
        for (int j = 0; j < TN2; j++) acc2[i][j] = 0ull;

    for (int k0 = 0; k0 < K; k0 += BK) {
        {
            const int ar = tid / BK, ac = tid % BK;
#pragma unroll
            for (int i = 0; i < BM; i += 256 / BK)
                As[ac][ar + i] = A[(size_t)(m0 + ar + i) * K + (k0 + ac)];
        }
        {
            const int br = tid / BN, bc = tid % BN;
#pragma unroll
            for (int i = 0; i < BK; i += 256 / BN)
                Bs[br + i][bc] = B[(size_t)(k0 + br + i) * N + (n0 + bc)];
        }
        __syncthreads();
#pragma unroll
        for (int kk = 0; kk < BK; kk++) {
            float ra[TM];
            float4 va = *reinterpret_cast<const float4*>(&As[kk][ty * TM]);
            ra[0] = va.x; ra[1] = va.y; ra[2] = va.z; ra[3] = va.w;
            ulonglong2 vb = *reinterpret_cast<const ulonglong2*>(&Bs[kk][tx * TN]);
            u64 rb2[TN2] = {vb.x, vb.y};
#pragma unroll
            for (int i = 0; i < TM; i++) {
                const u64 a2 = pack2f(ra[i], ra[i]);
#pragma unroll
                for (int j = 0; j < TN2; j++) ffma2(acc2[i][j], a2, rb2[j]);
            }
        }
        __syncthreads();
    }
#pragma unroll
    for (int i = 0; i < TM; i++) {
        const int row = m0 + ty * TM + i;
#pragma unroll
        for (int j = 0; j < TN2; j++) {
            float v0, v1;
            unpack2f(acc2[i][j], v0, v1);
            const int col = n0 + tx * TN + 2 * j;
            *reinterpret_cast<float2*>(&Cout[(size_t)row * N + col]) =
                make_float2(v0, v1);
        }
    }
}

// ===================== attention (emits split-bf16 G directly) ==============
__global__ void __launch_bounds__(256)
attn_kernel(const float* __restrict__ H, const float* __restrict__ R,
            __nv_bfloat16* __restrict__ Gsplit)
{
    const int m = blockIdx.x, tid = threadIdx.x;
    const int wid = tid >> 5, lane = tid & 31;

    __shared__ float sH[Wn * Dd];
    __shared__ float sR[Dd];
    __shared__ float sAlpha[Wn];

    const float* Hm = H + (size_t)m * Wn * Dd;
    const float* Rm = R + (size_t)m * Dd;

    for (int i = tid; i < Wn * Dd; i += 256) sH[i] = Hm[i];
    for (int d = tid; d < Dd; d += 256) sR[d] = Rm[d];
    __syncthreads();

    const float* Hw = sH + wid * Dd;
    float s = 0.f;
    for (int d = lane; d < Dd; d += 32) s = fmaf(Hw[d], sR[d], s);
#pragma unroll
    for (int o = 16; o > 0; o >>= 1) s += __shfl_xor_sync(0xffffffffu, s, o);
    if (lane == 0) sAlpha[wid] = s;
    __syncthreads();

    float mx = -INFINITY;
#pragma unroll
    for (int w = 0; w < Wn; w++) mx = fmaxf(mx, sAlpha[w]);
    float a[Wn], den = 0.f;
#pragma unroll
    for (int w = 0; w < Wn; w++) { a[w] = expf(sAlpha[w] - mx); den += a[w]; }
    const float inv = 1.f / den;

    // weighted sum, emitted as A-side hi/lo triple: [hi | hi | lo]
    __nv_bfloat16* grow = Gsplit + (size_t)m * KX2;
    for (int d = tid; d < Dd; d += 256) {
        float g = 0.f;
#pragma unroll
        for (int w = 0; w < Wn; w++) g = fmaf(a[w], sH[w * Dd + d], g);
        g *= inv;
        __nv_bfloat16 hi = __float2bfloat16(g);
        __nv_bfloat16 lo = __float2bfloat16(g - __bfloat162float(hi));
        grow[d]            = hi;
        grow[KP2 + d]      = hi;
        grow[2 * KP2 + d]  = lo;
    }
}

// ===================== residual + LayerNorm =================================
__global__ void __launch_bounds__(256)
resid_ln_kernel(const float* __restrict__ LO, const float* __restrict__ WTD,
                const float* __restrict__ gamma, const float* __restrict__ beta,
                float* __restrict__ out)
{
    const int m = blockIdx.x, tid = threadIdx.x;
    const int wid = tid >> 5, lane = tid & 31;
    const float* lo = LO + (size_t)m * Dd;
    const float* wt = WTD + (size_t)m * Dd;

    float x[3], s = 0.f, ss = 0.f;
#pragma unroll
    for (int i = 0; i < 3; i++) {
        const int d = tid + i * 256;
        const float v = lo[d] + wt[d];
        x[i] = v; s += v; ss += v * v;
    }
    __shared__ float rs[8], rss[8];
#pragma unroll
    for (int o = 16; o > 0; o >>= 1) {
        s  += __shfl_xor_sync(0xffffffffu, s, o);
        ss += __shfl_xor_sync(0xffffffffu, ss, o);
    }
    if (lane == 0) { rs[wid] = s; rss[wid] = ss; }
    __syncthreads();
    s = 0.f; ss = 0.f;
#pragma unroll
    for (int w = 0; w < 8; w++) { s += rs[w]; ss += rss[w]; }
    const float mu = s * (1.f / Dd);
    const float var = ss * (1.f / Dd) - mu * mu;
    const float rstd = rsqrtf(var + 1e-12f);
#pragma unroll
    for (int i = 0; i < 3; i++) {
        const int d = tid + i * 256;
        out[(size_t)m * Dd + d] = (x[i] - mu) * rstd * gamma[d] + beta[d];
    }
}

// ===================== launch ===============================================
// Order chosen so launch #6 (ncu -s 5 -c 1) is hgemm H.
extern "C" void kernel_launch(void* const* d_in, const int* in_sizes, int n_in,
                              void* d_out, int out_size)
{
    (void)in_sizes; (void)n_in; (void)out_size;
    const float* WE  = (const float*)d_in[0];
    const float* LO  = (const float*)d_in[1];
    const float* Wt  = (const float*)d_in[2];
    const float* bt  = (const float*)d_in[3];
    const float* Ww  = (const float*)d_in[4];
    const float* bw  = (const float*)d_in[5];
    const float* AW  = (const float*)d_in[6];
    const float* gam = (const float*)d_in[7];
    const float* bet = (const float*)d_in[8];
    float* out = (float*)d_out;

    float *pH, *pC, *pR, *pW;
    __nv_bfloat16 *pA1, *pB1, *pA2, *pB2, *pB3;
    cudaGetSymbolAddress((void**)&pH, g_H);
    cudaGetSymbolAddress((void**)&pC, g_C);
    cudaGetSymbolAddress((void**)&pR, g_R);
    cudaGetSymbolAddress((void**)&pW, g_WTD);
    cudaGetSymbolAddress((void**)&pA1, gA1);
    cudaGetSymbolAddress((void**)&pB1, gB1);
    cudaGetSymbolAddress((void**)&pA2, gA2);
    cudaGetSymbolAddress((void**)&pB2, gB2);
    cudaGetSymbolAddress((void**)&pB3, gB3);

    cudaFuncSetAttribute(hgemm_kernel<true>,
                         cudaFuncAttributeMaxDynamicSharedMemorySize, HG_SMEM);
    cudaFuncSetAttribute(hgemm_kernel<false>,
                         cudaFuncAttributeMaxDynamicSharedMemorySize, HG_SMEM);

    // 1-4: input splits
    split_kernel<false, false><<<(M1 * KP1 + 255) / 256, 256>>>(WE, pA1, M1, Ee, KP1);
    split_kernel<true,  false><<<(Dd * KP1 + 255) / 256, 256>>>(Wt, pB1, Dd, Ee, KP1);
    split_kernel<false, false><<<(M2 * KP2 + 255) / 256, 256>>>(LO, pA2, M2, Dd, KP2);
    split_kernel<true,  false><<<(Dd * KP2 + 255) / 256, 256>>>(Ww, pB3, Dd, Dd, KP2);

    // 5: C = attn_W @ Ww (fp32)
    sgemm64_kernel<<<dim3(Dd / 64, Dd / 64), 256>>>(AW, Ww, pC, Dd, Dd);

    // 6: H = tanh(WE @ Wt^T + bt)   [65536 x 768], K'=672   <-- ncu capture
    hgemm_kernel<true><<<dim3(Dd / 128, M1 / 128), 256, HG_SMEM>>>(
        pA1, pB1, bt, pH, KX1, Dd);

    // 7: split C^T for the NT tensor GEMM
    split_kernel<true, true><<<(Dd * KP2 + 255) / 256, 256>>>(pC, pB2, Dd, Dd, KP2);

    // 8: R = LO @ (attn_W@Ww)       [8192 x 768], K'=2304
    hgemm_kernel<false><<<dim3(Dd / 128, M2 / 128), 256, HG_SMEM>>>(
        pA2, pB2, nullptr, pR, KX2, Dd);

    // 9: softmax attention -> split-bf16 G (A-side triple), reusing gA2
    attn_kernel<<<M2, 256>>>(pH, pR, pA2);

    // 10: WTD = G @ Ww^T + bw
    hgemm_kernel<false><<<dim3(Dd / 128, M2 / 128), 256, HG_SMEM>>>(
        pA2, pB3, bw, pW, KX2, Dd);

    // 11: out = LayerNorm(LO + WTD)
    resid_ln_kernel<<<M2, 256>>>(LO, pW, gam, bet, out);
}

// round 14
// speedup vs baseline: 3.0373x; 1.2185x over previous
#include <cuda_runtime.h>
#include <cuda_fp16.h>
#include <math.h>
#include <stdint.h>

// Problem dims (fixed by the dataset)
constexpr int Wn = 8, Ee = 200, Dd = 768;
constexpr int M1 = 65536;          // B*L*W rows for GEMM H
constexpr int M2 = 8192;           // B*L rows
constexpr int KP1 = 224;           // K pad for E=200 (multiple of 32)
constexpr int KX1 = 2 * KP1;       // 448  = split-K' for GEMM H
constexpr int KP2 = 768;
constexpr int KX2 = 2 * KP2;       // 1536 = split-K' for GEMM R / WTD

// ---- scratch (__device__ globals; no cudaMalloc allowed) ----
__device__ __align__(16) __half g_H[(size_t)M1 * Dd];   // fp16 H (attn-only consumer)
__device__ float g_C[Dd * Dd];
__device__ __align__(16) __half g_R[M2 * Dd];           // fp16 R (attn-only consumer)
__device__ float g_WTD[M2 * Dd];
__device__ __align__(16) __half gA1[(size_t)M1 * KX1];  // WE split [hi|lo]
__device__ __align__(16) __half gB1[(size_t)Dd * KX1];  // Wt split [hi|hi]
__device__ __align__(16) __half gA2[(size_t)M2 * KX2];  // LO split, then G split [hi|lo]
__device__ __align__(16) __half gB2[(size_t)Dd * KX2];  // (AW@Ww)^T split [hi|hi]
__device__ __align__(16) __half gB3[(size_t)Dd * KX2];  // Ww split [hi|hi]

using u64 = unsigned long long;

// ===================== PTX helpers (compute_103-safe: sm_80+ subset) ========
__device__ __forceinline__ uint32_t smem_u32(const void* p) {
    uint32_t a;
    asm("{ .reg .u64 t; cvta.to.shared.u64 t, %1; cvt.u32.u64 %0, t; }"
        : "=r"(a) : "l"(p));
    return a;
}
__device__ __forceinline__ void cp16(uint32_t dst, const void* src) {
    asm volatile("cp.async.cg.shared.global [%0], [%1], 16;"
                 :: "r"(dst), "l"(src));
}
#define CP_COMMIT() asm volatile("cp.async.commit_group;" ::: "memory")
template <int N>
__device__ __forceinline__ void cp_wait() {
    asm volatile("cp.async.wait_group %0;" :: "n"(N) : "memory");
}
__device__ __forceinline__ void ldsm4(uint32_t& r0, uint32_t& r1,
                                      uint32_t& r2, uint32_t& r3, uint32_t a) {
    asm volatile("ldmatrix.sync.aligned.m8n8.x4.shared.b16 {%0,%1,%2,%3}, [%4];"
                 : "=r"(r0), "=r"(r1), "=r"(r2), "=r"(r3) : "r"(a));
}
__device__ __forceinline__ void mma_fp16(float* acc, const uint32_t* a,
                                         const uint32_t* b) {
    asm volatile(
        "mma.sync.aligned.m16n8k16.row.col.f32.f16.f16.f32 "
        "{%0,%1,%2,%3}, {%4,%5,%6,%7}, {%8,%9}, {%0,%1,%2,%3};"
        : "+f"(acc[0]), "+f"(acc[1]), "+f"(acc[2]), "+f"(acc[3])
        : "r"(a[0]), "r"(a[1]), "r"(a[2]), "r"(a[3]), "r"(b[0]), "r"(b[1]));
}

// ===================== Tensor-core GEMM (HMMA fp16, NT, 3-stage) ============
// Out[m,n] = act( sum_k A[m,k]*B[n,k] + bias[n] ), A [M,Kp], B [N,Kp] fp16.
// Block tile 128x128x32, 8 warps (2m x 4n, 64x32 each), 3-stage cp.async.
constexpr int SS = 40;        // SMEM row stride in fp16 (32 + 8 pad; 80B)
constexpr int STAGES = 3;
constexpr int HG_SMEM = 2 * STAGES * 128 * SS * 2;    // 61440 B

template <bool DO_TANH, typename OutT>
__global__ void __launch_bounds__(256, 2)
hgemm_kernel(const __half* __restrict__ A, const __half* __restrict__ B,
             const float* __restrict__ bias, OutT* __restrict__ Out,
             int Kp, int Nglob)
{
    extern __shared__ __align__(16) char dynsmem[];
    __half* sA = reinterpret_cast<__half*>(dynsmem);
    __half* sB = sA + STAGES * 128 * SS;

    const int tid = threadIdx.x, wid = tid >> 5, lane = tid & 31;
    const int wm = wid >> 2, wn = wid & 3;             // 2 x 4 warp grid
    const int m0 = blockIdx.y * 128, n0 = blockIdx.x * 128;
    const int NC = Kp / 32;

    uint32_t aBase[STAGES], bBase[STAGES];
#pragma unroll
    for (int s = 0; s < STAGES; s++) {
        aBase[s] = smem_u32(sA + s * 128 * SS);
        bBase[s] = smem_u32(sB + s * 128 * SS);
    }

    // global->smem loader: 512 x 16B per operand tile; 2 per thread each
    const int lr = tid >> 2;           // row 0..63; two iters cover 128
    const int lc = tid & 3;            // 16B column chunk 0..3
    const uint32_t doff = (uint32_t)(lr * SS + lc * 8) * 2;
    auto load_tile = [&](int s, int kc) {
        const __half* ag = A + (size_t)(m0 + lr) * Kp + kc * 32 + lc * 8;
        const __half* bg = B + (size_t)(n0 + lr) * Kp + kc * 32 + lc * 8;
        cp16(aBase[s] + doff, ag);
        cp16(aBase[s] + doff + 64 * SS * 2, ag + (size_t)64 * Kp);
        cp16(bBase[s] + doff, bg);
        cp16(bBase[s] + doff + 64 * SS * 2, bg + (size_t)64 * Kp);
    };

    float acc[4][4][4];
#pragma unroll
    for (int f = 0; f < 4; f++)
#pragma unroll
        for (int g = 0; g < 4; g++)
#pragma unroll
            for (int x = 0; x < 4; x++) acc[f][g][x] = 0.f;

    // ldmatrix address components (within a stage, in bytes)
    const uint32_t aRow = (uint32_t)(wm * 64 + (lane & 15)) * SS * 2;
    const uint32_t aKof = (uint32_t)((lane >> 1) & 8) * 2;
    const uint32_t bRow =
        (uint32_t)(wn * 32 + ((lane >> 4) << 3) + (lane & 7)) * SS * 2;
    const uint32_t bKof = (uint32_t)(lane & 8) * 2;

    load_tile(0, 0); CP_COMMIT();
    load_tile(1, 1); CP_COMMIT();

    int buf = 0;
    for (int c = 0; c < NC; c++) {
        if (c + 1 < NC) cp_wait<1>(); else cp_wait<0>();
        __syncthreads();
        if (c + 2 < NC) { load_tile((buf + 2) % STAGES, c + 2); CP_COMMIT(); }

#pragma unroll
        for (int kk = 0; kk < 2; kk++) {
            uint32_t af[4][4];
#pragma unroll
            for (int f = 0; f < 4; f++) {
                uint32_t addr = aBase[buf] + aRow + (uint32_t)(f * 16) * SS * 2 +
                                (uint32_t)(kk * 16) * 2 + aKof;
                ldsm4(af[f][0], af[f][1], af[f][2], af[f][3], addr);
            }
            uint32_t bf[4][2];
#pragma unroll
            for (int p = 0; p < 2; p++) {
                uint32_t addr = bBase[buf] + bRow + (uint32_t)(p * 16) * SS * 2 +
                                (uint32_t)(kk * 16) * 2 + bKof;
                ldsm4(bf[2 * p][0], bf[2 * p][1], bf[2 * p + 1][0],
                      bf[2 * p + 1][1], addr);
            }
#pragma unroll
            for (int f = 0; f < 4; f++)
#pragma unroll
                for (int g = 0; g < 4; g++)
                    mma_fp16(acc[f][g], af[f], bf[g]);
        }
        buf = (buf + 1) % STAGES;
    }

    // epilogue: c-frag m16n8 -> rows t/4, t/4+8; cols 2(t%4), +1
#pragma unroll
    for (int f = 0; f < 4; f++) {
        const int row0 = m0 + wm * 64 + f * 16 + (lane >> 2);
#pragma unroll
        for (int g = 0; g < 4; g++) {
            const int col = n0 + wn * 32 + g * 8 + 2 * (lane & 3);
            float v0 = acc[f][g][0], v1 = acc[f][g][1];
            float v2 = acc[f][g][2], v3 = acc[f][g][3];
            if (bias) {
                const float b0 = bias[col], b1 = bias[col + 1];
                v0 += b0; v1 += b1; v2 += b0; v3 += b1;
            }
            if (DO_TANH) {
                v0 = tanhf(v0); v1 = tanhf(v1);
                v2 = tanhf(v2); v3 = tanhf(v3);
            }
            if (sizeof(OutT) == 2) {  // fp16 output
                __half2* o0 = reinterpret_cast<__half2*>(
                    (__half*)Out + (size_t)row0 * Nglob + col);
                __half2* o1 = reinterpret_cast<__half2*>(
                    (__half*)Out + (size_t)(row0 + 8) * Nglob + col);
                *o0 = __floats2half2_rn(v0, v1);
                *o1 = __floats2half2_rn(v2, v3);
            } else {
                *reinterpret_cast<float2*>(
                    (float*)Out + (size_t)row0 * Nglob + col) =
                    make_float2(v0, v1);
                *reinterpret_cast<float2*>(
                    (float*)Out + (size_t)(row0 + 8) * Nglob + col) =
                    make_float2(v2, v3);
            }
        }
    }
}

// ===================== split-to-fp16 2-term (K-concatenated) ================
// A side: [hi | lo] with hi=f16(x), lo=f16(x-hi).  B side: [hi | hi].
// Product (Ahi+Alo).Bhi = A.Bhi; residual A.Blo ~ 2^-11.
template <bool BSIDE, bool TRANS>
__global__ void split_kernel(const float* __restrict__ src,
                             __half* __restrict__ dst,
                             int Msz, int Ksrc, int Kpad)
{
    int idx = blockIdx.x * 256 + threadIdx.x;
    if (idx >= Msz * Kpad) return;
    int m = idx / Kpad, k = idx % Kpad;
    float x = 0.f;
    if (k < Ksrc)
        x = TRANS ? src[(size_t)k * Msz + m] : src[(size_t)m * Ksrc + k];
    __half hi = __float2half_rn(x);
    __half lo = BSIDE ? hi : __float2half_rn(x - __half2float(hi));
    size_t base = (size_t)m * 2 * Kpad;
    dst[base + k]        = hi;
    dst[base + Kpad + k] = lo;
}

// ===================== fp32 SGEMM (tiny 768^3: C = attn_W @ Ww) =============
__device__ __forceinline__ void ffma2(u64& d, u64 a, u64 b) {
    asm("fma.rn.f32x2 %0, %1, %2, %0;" : "+l"(d) : "l"(a), "l"(b));
}
__device__ __forceinline__ u64 pack2f(float x, float y) {
    u64 r; asm("mov.b64 %0, {%1, %2};" : "=l"(r) : "f"(x), "f"(y)); return r;
}
__device__ __forceinline__ void unpack2f(u64 v, float& x, float& y) {
    asm("mov.b64 {%0, %1}, %2;" : "=f"(x), "=f"(y) : "l"(v));
}

__global__ void __launch_bounds__(256)
sgemm64_kernel(const float* __restrict__ A, const float* __restrict__ B,
               float* __restrict__ Cout, int N, int K)
{
    constexpr int BM = 64, BN = 64, BK = 16, TM = 4, TN = 4, TN2 = 2;
    __shared__ float As[BK][BM];
    __shared__ float Bs[BK][BN];
    const int tid = threadIdx.x;
    const int m0 = blockIdx.y * BM, n0 = blockIdx.x * BN;
    const int tx = tid % (BN / TN), ty = tid / (BN / TN);

    u64 acc2[TM][TN2];
#pragma unroll
    for (int i = 0; i < TM; i++)
#pragma unroll
        for (int j = 0; j < TN2; j++) acc2[i][j] = 0ull;

    for (int k0 = 0; k0 < K; k0 += BK) {
        {
            const int ar = tid / BK, ac = tid % BK;
#pragma unroll
            for (int i = 0; i < BM; i += 256 / BK)
                As[ac][ar + i] = A[(size_t)(m0 + ar + i) * K + (k0 + ac)];
        }
        {
            const int br = tid / BN, bc = tid % BN;
#pragma unroll
            for (int i = 0; i < BK; i += 256 / BN)
                Bs[br + i][bc] = B[(size_t)(k0 + br + i) * N + (n0 + bc)];
        }
        __syncthreads();
#pragma unroll
        for (int kk = 0; kk < BK; kk++) {
            float ra[TM];
            float4 va = *reinterpret_cast<const float4*>(&As[kk][ty * TM]);
            ra[0] = va.x; ra[1] = va.y; ra[2] = va.z; ra[3] = va.w;
            ulonglong2 vb = *reinterpret_cast<const ulonglong2*>(&Bs[kk][tx * TN]);
            u64 rb2[TN2] = {vb.x, vb.y};
#pragma unroll
            for (int i = 0; i < TM; i++) {
                const u64 a2 = pack2f(ra[i], ra[i]);
#pragma unroll
                for (int j = 0; j < TN2; j++) ffma2(acc2[i][j], a2, rb2[j]);
            }
        }
        __syncthreads();
    }
#pragma unroll
    for (int i = 0; i < TM; i++) {
        const int row = m0 + ty * TM + i;
#pragma unroll
        for (int j = 0; j < TN2; j++) {
            float v0, v1;
            unpack2f(acc2[i][j], v0, v1);
            const int col = n0 + tx * TN + 2 * j;
            *reinterpret_cast<float2*>(&Cout[(size_t)row * N + col]) =
                make_float2(v0, v1);
        }
    }
}

// ===================== attention (fp16 H/R in, split-fp16 G out) ============
__global__ void __launch_bounds__(256)
attn_kernel(const __half* __restrict__ H, const __half* __restrict__ R,
            __half* __restrict__ Gsplit)
{
    const int m = blockIdx.x, tid = threadIdx.x;
    const int wid = tid >> 5, lane = tid & 31;

    __shared__ float sH[Wn * Dd];
    __shared__ float sR[Dd];
    __shared__ float sAlpha[Wn];

    const __half2* Hm2 = reinterpret_cast<const __half2*>(H + (size_t)m * Wn * Dd);
    const __half2* Rm2 = reinterpret_cast<const __half2*>(R + (size_t)m * Dd);

    for (int i = tid; i < Wn * Dd / 2; i += 256) {
        float2 f = __half22float2(Hm2[i]);
        sH[2 * i] = f.x; sH[2 * i + 1] = f.y;
    }
    for (int i = tid; i < Dd / 2; i += 256) {
        float2 f = __half22float2(Rm2[i]);
        sR[2 * i] = f.x; sR[2 * i + 1] = f.y;
    }
    __syncthreads();

    const float* Hw = sH + wid * Dd;
    float s = 0.f;
    for (int d = lane; d < Dd; d += 32) s = fmaf(Hw[d], sR[d], s);
#pragma unroll
    for (int o = 16; o > 0; o >>= 1) s += __shfl_xor_sync(0xffffffffu, s, o);
    if (lane == 0) sAlpha[wid] = s;
    __syncthreads();

    float mx = -INFINITY;
#pragma unroll
    for (int w = 0; w < Wn; w++) mx = fmaxf(mx, sAlpha[w]);
    float a[Wn], den = 0.f;
#pragma unroll
    for (int w = 0; w < Wn; w++) { a[w] = expf(sAlpha[w] - mx); den += a[w]; }
    const float inv = 1.f / den;

    // weighted sum, emitted as A-side fp16 pair: [hi | lo]
    __half* grow = Gsplit + (size_t)m * KX2;
    for (int d = tid; d < Dd; d += 256) {
        float g = 0.f;
#pragma unroll
        for (int w = 0; w < Wn; w++) g = fmaf(a[w], sH[w * Dd + d], g);
        g *= inv;
        __half hi = __float2half_rn(g);
        __half lo = __float2half_rn(g - __half2float(hi));
        grow[d]       = hi;
        grow[KP2 + d] = lo;
    }
}

// ===================== residual + LayerNorm =================================
__global__ void __launch_bounds__(256)
resid_ln_kernel(const float* __restrict__ LO, const float* __restrict__ WTD,
                const float* __restrict__ gamma, const float* __restrict__ beta,
                float* __restrict__ out)
{
    const int m = blockIdx.x, tid = threadIdx.x;
    const int wid = tid >> 5, lane = tid & 31;
    const float* lo = LO + (size_t)m * Dd;
    const float* wt = WTD + (size_t)m * Dd;

    float x[3], s = 0.f, ss = 0.f;
#pragma unroll
    for (int i = 0; i < 3; i++) {
        const int d = tid + i * 256;
        const float v = lo[d] + wt[d];
        x[i] = v; s += v; ss += v * v;
    }
    __shared__ float rs[8], rss[8];
#pragma unroll
    for (int o = 16; o > 0; o >>= 1) {
        s  += __shfl_xor_sync(0xffffffffu, s, o);
        ss += __shfl_xor_sync(0xffffffffu, ss, o);
    }
    if (lane == 0) { rs[wid] = s; rss[wid] = ss; }
    __syncthreads();
    s = 0.f; ss = 0.f;
#pragma unroll
    for (int w = 0; w < 8; w++) { s += rs[w]; ss += rss[w]; }
    const float mu = s * (1.f / Dd);
    const float var = ss * (1.f / Dd) - mu * mu;
    const float rstd = rsqrtf(var + 1e-12f);
#pragma unroll
    for (int i = 0; i < 3; i++) {
        const int d = tid + i * 256;
        out[(size_t)m * Dd + d] = (x[i] - mu) * rstd * gamma[d] + beta[d];
    }
}

// ===================== launch ===============================================
// Order chosen so launch #6 (ncu -s 5 -c 1) is hgemm H.
extern "C" void kernel_launch(void* const* d_in, const int* in_sizes, int n_in,
                              void* d_out, int out_size)
{
    (void)in_sizes; (void)n_in; (void)out_size;
    const float* WE  = (const float*)d_in[0];
    const float* LO  = (const float*)d_in[1];
    const float* Wt  = (const float*)d_in[2];
    const float* bt  = (const float*)d_in[3];
    const float* Ww  = (const float*)d_in[4];
    const float* bw  = (const float*)d_in[5];
    const float* AW  = (const float*)d_in[6];
    const float* gam = (const float*)d_in[7];
    const float* bet = (const float*)d_in[8];
    float* out = (float*)d_out;

    float *pC, *pW;
    __half *pH, *pR, *pA1, *pB1, *pA2, *pB2, *pB3;
    cudaGetSymbolAddress((void**)&pH, g_H);
    cudaGetSymbolAddress((void**)&pC, g_C);
    cudaGetSymbolAddress((void**)&pR, g_R);
    cudaGetSymbolAddress((void**)&pW, g_WTD);
    cudaGetSymbolAddress((void**)&pA1, gA1);
    cudaGetSymbolAddress((void**)&pB1, gB1);
    cudaGetSymbolAddress((void**)&pA2, gA2);
    cudaGetSymbolAddress((void**)&pB2, gB2);
    cudaGetSymbolAddress((void**)&pB3, gB3);

    cudaFuncSetAttribute((const void*)hgemm_kernel<true, __half>,
                         cudaFuncAttributeMaxDynamicSharedMemorySize, HG_SMEM);
    cudaFuncSetAttribute((const void*)hgemm_kernel<false, __half>,
                         cudaFuncAttributeMaxDynamicSharedMemorySize, HG_SMEM);
    cudaFuncSetAttribute((const void*)hgemm_kernel<false, float>,
                         cudaFuncAttributeMaxDynamicSharedMemorySize, HG_SMEM);

    // 1-4: input splits
    split_kernel<false, false><<<(M1 * KP1 + 255) / 256, 256>>>(WE, pA1, M1, Ee, KP1);
    split_kernel<true,  false><<<(Dd * KP1 + 255) / 256, 256>>>(Wt, pB1, Dd, Ee, KP1);
    split_kernel<false, false><<<(M2 * KP2 + 255) / 256, 256>>>(LO, pA2, M2, Dd, KP2);
    split_kernel<true,  false><<<(Dd * KP2 + 255) / 256, 256>>>(Ww, pB3, Dd, Dd, KP2);

    // 5: C = attn_W @ Ww (fp32)
    sgemm64_kernel<<<dim3(Dd / 64, Dd / 64), 256>>>(AW, Ww, pC, Dd, Dd);

    // 6: H = tanh(WE @ Wt^T + bt)   [65536 x 768], K'=448   <-- ncu capture
    hgemm_kernel<true, __half><<<dim3(Dd / 128, M1 / 128), 256, HG_SMEM>>>(
        pA1, pB1, bt, pH, KX1, Dd);

    // 7: split C^T for the NT tensor GEMM
    split_kernel<true, true><<<(Dd * KP2 + 255) / 256, 256>>>(pC, pB2, Dd, Dd, KP2);

    // 8: R = LO @ (attn_W@Ww)       [8192 x 768], K'=1536
    hgemm_kernel<false, __half><<<dim3(Dd / 128, M2 / 128), 256, HG_SMEM>>>(
        pA2, pB2, nullptr, pR, KX2, Dd);

    // 9: softmax attention -> split-fp16 G (A-side pair), reusing gA2
    attn_kernel<<<M2, 256>>>(pH, pR, pA2);

    // 10: WTD = G @ Ww^T + bw  (fp32 out)
    hgemm_kernel<false, float><<<dim3(Dd / 128, M2 / 128), 256, HG_SMEM>>>(
        pA2, pB3, bw, pW, KX2, Dd);

    // 11: out = LayerNorm(LO + WTD)
    resid_ln_kernel<<<M2, 256>>>(LO, pW, gam, bet, out);
}

// round 16
// speedup vs baseline: 4.0877x; 1.3458x over previous
#include <cuda_runtime.h>
#include <cuda_fp16.h>
#include <math.h>
#include <stdint.h>

// Problem dims (fixed by the dataset)
constexpr int Wn = 8, Ee = 200, Dd = 768;
constexpr int M1 = 65536;          // B*L*W rows for GEMM H
constexpr int M2 = 8192;           // B*L rows
constexpr int KP1 = 224;           // K pad for E=200 (multiple of 32)
constexpr int KP2 = 768;

// ---- scratch (__device__ globals; no cudaMalloc allowed) ----
__device__ __align__(16) __half g_H[(size_t)M1 * Dd];   // fp16 H (attn-only consumer)
__device__ float g_C[Dd * Dd];
__device__ __align__(16) __half g_R[M2 * Dd];           // fp16 R (attn-only consumer)
__device__ float g_WTD[M2 * Dd];
__device__ __align__(16) __half gA1[(size_t)M1 * KP1];  // WE  fp16 (padded)
__device__ __align__(16) __half gB1[(size_t)Dd * KP1];  // Wt  fp16 (padded)
__device__ __align__(16) __half gA2[(size_t)M2 * KP2];  // LO fp16, then G fp16
__device__ __align__(16) __half gB2[(size_t)Dd * KP2];  // (AW@Ww)^T fp16
__device__ __align__(16) __half gB3[(size_t)Dd * KP2];  // Ww fp16

using u64 = unsigned long long;

// ===================== PTX helpers (compute_103-safe: sm_80+ subset) ========
__device__ __forceinline__ uint32_t smem_u32(const void* p) {
    uint32_t a;
    asm("{ .reg .u64 t; cvta.to.shared.u64 t, %1; cvt.u32.u64 %0, t; }"
        : "=r"(a) : "l"(p));
    return a;
}
__device__ __forceinline__ void cp16(uint32_t dst, const void* src) {
    asm volatile("cp.async.cg.shared.global [%0], [%1], 16;"
                 :: "r"(dst), "l"(src));
}
#define CP_COMMIT() asm volatile("cp.async.commit_group;" ::: "memory")
template <int N>
__device__ __forceinline__ void cp_wait() {
    asm volatile("cp.async.wait_group %0;" :: "n"(N) : "memory");
}
__device__ __forceinline__ void ldsm4(uint32_t& r0, uint32_t& r1,
                                      uint32_t& r2, uint32_t& r3, uint32_t a) {
    asm volatile("ldmatrix.sync.aligned.m8n8.x4.shared.b16 {%0,%1,%2,%3}, [%4];"
                 : "=r"(r0), "=r"(r1), "=r"(r2), "=r"(r3) : "r"(a));
}
__device__ __forceinline__ void mma_fp16(float* acc, const uint32_t* a,
                                         const uint32_t* b) {
    asm volatile(
        "mma.sync.aligned.m16n8k16.row.col.f32.f16.f16.f32 "
        "{%0,%1,%2,%3}, {%4,%5,%6,%7}, {%8,%9}, {%0,%1,%2,%3};"
        : "+f"(acc[0]), "+f"(acc[1]), "+f"(acc[2]), "+f"(acc[3])
        : "r"(a[0]), "r"(a[1]), "r"(a[2]), "r"(a[3]), "r"(b[0]), "r"(b[1]));
}

// ===================== Tensor-core GEMM (HMMA fp16, NT, 3-stage) ============
// Out[m,n] = act( sum_k A[m,k]*B[n,k] + bias[n] ), A [M,Kp], B [N,Kp] fp16.
// Block tile 128x128x32, 8 warps (2m x 4n, 64x32 each), 3-stage cp.async.
constexpr int SS = 40;        // SMEM row stride in fp16 (32 + 8 pad; 80B)
constexpr int STAGES = 3;
constexpr int HG_SMEM = 2 * STAGES * 128 * SS * 2;    // 61440 B

template <bool DO_TANH, typename OutT>
__global__ void __launch_bounds__(256, 2)
hgemm_kernel(const __half* __restrict__ A, const __half* __restrict__ B,
             const float* __restrict__ bias, OutT* __restrict__ Out,
             int Kp, int Nglob)
{
    extern __shared__ __align__(16) char dynsmem[];
    __half* sA = reinterpret_cast<__half*>(dynsmem);
    __half* sB = sA + STAGES * 128 * SS;

    const int tid = threadIdx.x, wid = tid >> 5, lane = tid & 31;
    const int wm = wid >> 2, wn = wid & 3;             // 2 x 4 warp grid
    const int m0 = blockIdx.y * 128, n0 = blockIdx.x * 128;
    const int NC = Kp / 32;

    uint32_t aBase[STAGES], bBase[STAGES];
#pragma unroll
    for (int s = 0; s < STAGES; s++) {
        aBase[s] = smem_u32(sA + s * 128 * SS);
        bBase[s] = smem_u32(sB + s * 128 * SS);
    }

    // global->smem loader: 512 x 16B per operand tile; 2 per thread each
    const int lr = tid >> 2;           // row 0..63; two iters cover 128
    const int lc = tid & 3;            // 16B column chunk 0..3
    const uint32_t doff = (uint32_t)(lr * SS + lc * 8) * 2;
    auto load_tile = [&](int s, int kc) {
        const __half* ag = A + (size_t)(m0 + lr) * Kp + kc * 32 + lc * 8;
        const __half* bg = B + (size_t)(n0 + lr) * Kp + kc * 32 + lc * 8;
        cp16(aBase[s] + doff, ag);
        cp16(aBase[s] + doff + 64 * SS * 2, ag + (size_t)64 * Kp);
        cp16(bBase[s] + doff, bg);
        cp16(bBase[s] + doff + 64 * SS * 2, bg + (size_t)64 * Kp);
    };

    float acc[4][4][4];
#pragma unroll
    for (int f = 0; f < 4; f++)
#pragma unroll
        for (int g = 0; g < 4; g++)
#pragma unroll
            for (int x = 0; x < 4; x++) acc[f][g][x] = 0.f;

    // ldmatrix address components (within a stage, in bytes)
    const uint32_t aRow = (uint32_t)(wm * 64 + (lane & 15)) * SS * 2;
    const uint32_t aKof = (uint32_t)((lane >> 1) & 8) * 2;
    const uint32_t bRow =
        (uint32_t)(wn * 32 + ((lane >> 4) << 3) + (lane & 7)) * SS * 2;
    const uint32_t bKof = (uint32_t)(lane & 8) * 2;

    load_tile(0, 0); CP_COMMIT();
    load_tile(1, 1); CP_COMMIT();

    int buf = 0;
    for (int c = 0; c < NC; c++) {
        if (c + 1 < NC) cp_wait<1>(); else cp_wait<0>();
        __syncthreads();
        if (c + 2 < NC) { load_tile((buf + 2) % STAGES, c + 2); CP_COMMIT(); }

#pragma unroll
        for (int kk = 0; kk < 2; kk++) {
            uint32_t af[4][4];
#pragma unroll
            for (int f = 0; f < 4; f++) {
                uint32_t addr = aBase[buf] + aRow + (uint32_t)(f * 16) * SS * 2 +
                                (uint32_t)(kk * 16) * 2 + aKof;
                ldsm4(af[f][0], af[f][1], af[f][2], af[f][3], addr);
            }
            uint32_t bf[4][2];
#pragma unroll
            for (int p = 0; p < 2; p++) {
                uint32_t addr = bBase[buf] + bRow + (uint32_t)(p * 16) * SS * 2 +
                                (uint32_t)(kk * 16) * 2 + bKof;
                ldsm4(bf[2 * p][0], bf[2 * p][1], bf[2 * p + 1][0],
                      bf[2 * p + 1][1], addr);
            }
#pragma unroll
            for (int f = 0; f < 4; f++)
#pragma unroll
                for (int g = 0; g < 4; g++)
                    mma_fp16(acc[f][g], af[f], bf[g]);
        }
        buf = (buf + 1) % STAGES;
    }

    // epilogue: c-frag m16n8 -> rows t/4, t/4+8; cols 2(t%4), +1
#pragma unroll
    for (int f = 0; f < 4; f++) {
        const int row0 = m0 + wm * 64 + f * 16 + (lane >> 2);
#pragma unroll
        for (int g = 0; g < 4; g++) {
            const int col = n0 + wn * 32 + g * 8 + 2 * (lane & 3);
            float v0 = acc[f][g][0], v1 = acc[f][g][1];
            float v2 = acc[f][g][2], v3 = acc[f][g][3];
            if (bias) {
                const float b0 = bias[col], b1 = bias[col + 1];
                v0 += b0; v1 += b1; v2 += b0; v3 += b1;
            }
            if (DO_TANH) {
                v0 = tanhf(v0); v1 = tanhf(v1);
                v2 = tanhf(v2); v3 = tanhf(v3);
            }
            if (sizeof(OutT) == 2) {  // fp16 output
                __half2* o0 = reinterpret_cast<__half2*>(
                    (__half*)Out + (size_t)row0 * Nglob + col);
                __half2* o1 = reinterpret_cast<__half2*>(
                    (__half*)Out + (size_t)(row0 + 8) * Nglob + col);
                *o0 = __floats2half2_rn(v0, v1);
                *o1 = __floats2half2_rn(v2, v3);
            } else {
                *reinterpret_cast<float2*>(
                    (float*)Out + (size_t)row0 * Nglob + col) =
                    make_float2(v0, v1);
                *reinterpret_cast<float2*>(
                    (float*)Out + (size_t)(row0 + 8) * Nglob + col) =
                    make_float2(v2, v3);
            }
        }
    }
}

// ===================== fp32 -> fp16 convert (padded, optional transpose) ====
// TRANS=false: dst[m,k] = src[m*Ksrc+k]   (src is [Msz,Ksrc] row-major)
// TRANS=true : dst[m,k] = src[k*Msz+m]    (src is [Ksrc,Msz] row-major)
template <bool TRANS>
__global__ void cvt_kernel(const float* __restrict__ src,
                           __half* __restrict__ dst,
                           int Msz, int Ksrc, int Kpad)
{
    int idx = blockIdx.x * 256 + threadIdx.x;
    if (idx >= Msz * Kpad) return;
    int m = idx / Kpad, k = idx % Kpad;
    float x = 0.f;
    if (k < Ksrc)
        x = TRANS ? src[(size_t)k * Msz + m] : src[(size_t)m * Ksrc + k];
    dst[(size_t)m * Kpad + k] = __float2half_rn(x);
}

// ===================== fp32 SGEMM (tiny 768^3: C = attn_W @ Ww) =============
__device__ __forceinline__ void ffma2(u64& d, u64 a, u64 b) {
    asm("fma.rn.f32x2 %0, %1, %2, %0;" : "+l"(d) : "l"(a), "l"(b));
}
__device__ __forceinline__ u64 pack2f(float x, float y) {
    u64 r; asm("mov.b64 %0, {%1, %2};" : "=l"(r) : "f"(x), "f"(y)); return r;
}
__device__ __forceinline__ void unpack2f(u64 v, float& x, float& y) {
    asm("mov.b64 {%0, %1}, %2;" : "=f"(x), "=f"(y) : "l"(v));
}

__global__ void __launch_bounds__(256)
sgemm64_kernel(const float* __restrict__ A, const float* __restrict__ B,
               float* __restrict__ Cout, int N, int K)
{
    constexpr int BM = 64, BN = 64, BK = 16, TM = 4, TN = 4, TN2 = 2;
    __shared__ float As[BK][BM];
    __shared__ float Bs[BK][BN];
    const int tid = threadIdx.x;
    const int m0 = blockIdx.y * BM, n0 = blockIdx.x * BN;
    const int tx = tid % (BN / TN), ty = tid / (BN / TN);

    u64 acc2[TM][TN2];
#pragma unroll
    for (int i = 0; i < TM; i++)
#pragma unroll
        for (int j = 0; j < TN2; j++) acc2[i][j] = 0ull;

    for (int k0 = 0; k0 < K; k0 += BK) {
        {
            const int ar = tid / BK, ac = tid % BK;
#pragma unroll
            for (int i = 0; i < BM; i += 256 / BK)
                As[ac][ar + i] = A[(size_t)(m0 + ar + i) * K + (k0 + ac)];
        }
        {
            const int br = tid / BN, bc = tid % BN;
#pragma unroll
            for (int i = 0; i < BK; i += 256 / BN)
                Bs[br + i][bc] = B[(size_t)(k0 + br + i) * N + (n0 + bc)];
        }
        __syncthreads();
#pragma unroll
        for (int kk = 0; kk < BK; kk++) {
            float ra[TM];
            float4 va = *reinterpret_cast<const float4*>(&As[kk][ty * TM]);
            ra[0] = va.x; ra[1] = va.y; ra[2] = va.z; ra[3] = va.w;
            ulonglong2 vb = *reinterpret_cast<const ulonglong2*>(&Bs[kk][tx * TN]);
            u64 rb2[TN2] = {vb.x, vb.y};
#pragma unroll
            for (int i = 0; i < TM; i++) {
                const u64 a2 = pack2f(ra[i], ra[i]);
#pragma unroll
                for (int j = 0; j < TN2; j++) ffma2(acc2[i][j], a2, rb2[j]);
            }
        }
        __syncthreads();
    }
#pragma unroll
    for (int i = 0; i < TM; i++) {
        const int row = m0 + ty * TM + i;
#pragma unroll
        for (int j = 0; j < TN2; j++) {
            float v0, v1;
            unpack2f(acc2[i][j], v0, v1);
            const int col = n0 + tx * TN + 2 * j;
            *reinterpret_cast<float2*>(&Cout[(size_t)row * N + col]) =
                make_float2(v0, v1);
        }
    }
}

// ===================== attention (fp16 H/R in, fp16 G out) ==================
__global__ void __launch_bounds__(256)
attn_kernel(const __half* __restrict__ H, const __half* __restrict__ R,
            __half* __restrict__ G)
{
    const int m = blockIdx.x, tid = threadIdx.x;
    const int wid = tid >> 5, lane = tid & 31;

    __shared__ float sH[Wn * Dd];
    __shared__ float sR[Dd];
    __shared__ float sAlpha[Wn];

    const __half2* Hm2 = reinterpret_cast<const __half2*>(H + (size_t)m * Wn * Dd);
    const __half2* Rm2 = reinterpret_cast<const __half2*>(R + (size_t)m * Dd);

    for (int i = tid; i < Wn * Dd / 2; i += 256) {
        float2 f = __half22float2(Hm2[i]);
        sH[2 * i] = f.x; sH[2 * i + 1] = f.y;
    }
    for (int i = tid; i < Dd / 2; i += 256) {
        float2 f = __half22float2(Rm2[i]);
        sR[2 * i] = f.x; sR[2 * i + 1] = f.y;
    }
    __syncthreads();

    const float* Hw = sH + wid * Dd;
    float s = 0.f;
    for (int d = lane; d < Dd; d += 32) s = fmaf(Hw[d], sR[d], s);
#pragma unroll
    for (int o = 16; o > 0; o >>= 1) s += __shfl_xor_sync(0xffffffffu, s, o);
    if (lane == 0) sAlpha[wid] = s;
    __syncthreads();

    float mx = -INFINITY;
#pragma unroll
    for (int w = 0; w < Wn; w++) mx = fmaxf(mx, sAlpha[w]);
    float a[Wn], den = 0.f;
#pragma unroll
    for (int w = 0; w < Wn; w++) { a[w] = expf(sAlpha[w] - mx); den += a[w]; }
    const float inv = 1.f / den;

    __half* grow = G + (size_t)m * KP2;
    for (int d = tid; d < Dd; d += 256) {
        float g = 0.f;
#pragma unroll
        for (int w = 0; w < Wn; w++) g = fmaf(a[w], sH[w * Dd + d], g);
        grow[d] = __float2half_rn(g * inv);
    }
}

// ===================== residual + LayerNorm =================================
__global__ void __launch_bounds__(256)
resid_ln_kernel(const float* __restrict__ LO, const float* __restrict__ WTD,
                const float* __restrict__ gamma, const float* __restrict__ beta,
                float* __restrict__ out)
{
    const int m = blockIdx.x, tid = threadIdx.x;
    const int wid = tid >> 5, lane = tid & 31;
    const float* lo = LO + (size_t)m * Dd;
    const float* wt = WTD + (size_t)m * Dd;

    float x[3], s = 0.f, ss = 0.f;
#pragma unroll
    for (int i = 0; i < 3; i++) {
        const int d = tid + i * 256;
        const float v = lo[d] + wt[d];
        x[i] = v; s += v; ss += v * v;
    }
    __shared__ float rs[8], rss[8];
#pragma unroll
    for (int o = 16; o > 0; o >>= 1) {
        s  += __shfl_xor_sync(0xffffffffu, s, o);
        ss += __shfl_xor_sync(0xffffffffu, ss, o);
    }
    if (lane == 0) { rs[wid] = s; rss[wid] = ss; }
    __syncthreads();
    s = 0.f; ss = 0.f;
#pragma unroll
    for (int w = 0; w < 8; w++) { s += rs[w]; ss += rss[w]; }
    const float mu = s * (1.f / Dd);
    const float var = ss * (1.f / Dd) - mu * mu;
    const float rstd = rsqrtf(var + 1e-12f);
#pragma unroll
    for (int i = 0; i < 3; i++) {
        const int d = tid + i * 256;
        out[(size_t)m * Dd + d] = (x[i] - mu) * rstd * gamma[d] + beta[d];
    }
}

// ===================== launch ===============================================
// Order chosen so launch #6 (ncu -s 5 -c 1) is hgemm H.
extern "C" void kernel_launch(void* const* d_in, const int* in_sizes, int n_in,
                              void* d_out, int out_size)
{
    (void)in_sizes; (void)n_in; (void)out_size;
    const float* WE  = (const float*)d_in[0];
    const float* LO  = (const float*)d_in[1];
    const float* Wt  = (const float*)d_in[2];
    const float* bt  = (const float*)d_in[3];
    const float* Ww  = (const float*)d_in[4];
    const float* bw  = (const float*)d_in[5];
    const float* AW  = (const float*)d_in[6];
    const float* gam = (const float*)d_in[7];
    const float* bet = (const float*)d_in[8];
    float* out = (float*)d_out;

    float *pC, *pW;
    __half *pH, *pR, *pA1, *pB1, *pA2, *pB2, *pB3;
    cudaGetSymbolAddress((void**)&pH, g_H);
    cudaGetSymbolAddress((void**)&pC, g_C);
    cudaGetSymbolAddress((void**)&pR, g_R);
    cudaGetSymbolAddress((void**)&pW, g_WTD);
    cudaGetSymbolAddress((void**)&pA1, gA1);
    cudaGetSymbolAddress((void**)&pB1, gB1);
    cudaGetSymbolAddress((void**)&pA2, gA2);
    cudaGetSymbolAddress((void**)&pB2, gB2);
    cudaGetSymbolAddress((void**)&pB3, gB3);

    cudaFuncSetAttribute((const void*)hgemm_kernel<true, __half>,
                         cudaFuncAttributeMaxDynamicSharedMemorySize, HG_SMEM);
    cudaFuncSetAttribute((const void*)hgemm_kernel<false, __half>,
                         cudaFuncAttributeMaxDynamicSharedMemorySize, HG_SMEM);
    cudaFuncSetAttribute((const void*)hgemm_kernel<false, float>,
                         cudaFuncAttributeMaxDynamicSharedMemorySize, HG_SMEM);

    // 1-4: input converts.  Wt [D,E] and Ww [D,D] are already [N,K] row-major
    // -> TRANS=false (the R15 bug was TRANS=true here).
    cvt_kernel<false><<<(M1 * KP1 + 255) / 256, 256>>>(WE, pA1, M1, Ee, KP1);
    cvt_kernel<false><<<(Dd * KP1 + 255) / 256, 256>>>(Wt, pB1, Dd, Ee, KP1);
    cvt_kernel<false><<<(M2 * KP2 + 255) / 256, 256>>>(LO, pA2, M2, Dd, KP2);
    cvt_kernel<false><<<(Dd * KP2 + 255) / 256, 256>>>(Ww, pB3, Dd, Dd, KP2);

    // 5: C = attn_W @ Ww (fp32)
    sgemm64_kernel<<<dim3(Dd / 64, Dd / 64), 256>>>(AW, Ww, pC, Dd, Dd);

    // 6: H = tanh(WE @ Wt^T + bt)   [65536 x 768], K=224   <-- ncu capture
    hgemm_kernel<true, __half><<<dim3(Dd / 128, M1 / 128), 256, HG_SMEM>>>(
        pA1, pB1, bt, pH, KP1, Dd);

    // 7: convert C^T for the NT tensor GEMM (C is [K,N] -> needs TRANS=true)
    cvt_kernel<true><<<(Dd * KP2 + 255) / 256, 256>>>(pC, pB2, Dd, Dd, KP2);

    // 8: R = LO @ (attn_W@Ww)       [8192 x 768], K=768
    hgemm_kernel<false, __half><<<dim3(Dd / 128, M2 / 128), 256, HG_SMEM>>>(
        pA2, pB2, nullptr, pR, KP2, Dd);

    // 9: softmax attention -> fp16 G, reusing gA2
    attn_kernel<<<M2, 256>>>(pH, pR, pA2);

    // 10: WTD = G @ Ww^T + bw  (fp32 out)
    hgemm_kernel<false, float><<<dim3(Dd / 128, M2 / 128), 256, HG_SMEM>>>(
        pA2, pB3, bw, pW, KP2, Dd);

    // 11: out = LayerNorm(LO + WTD)
    resid_ln_kernel<<<M2, 256>>>(LO, pW, gam, bet, out);
}

// round 17
// speedup vs baseline: 4.3729x; 1.0698x over previous
#include <cuda_runtime.h>
#include <cuda_fp16.h>
#include <math.h>
#include <stdint.h>

// Problem dims (fixed by the dataset)
constexpr int Wn = 8, Ee = 200, Dd = 768;
constexpr int M1 = 65536;          // B*L*W rows for GEMM H
constexpr int M2 = 8192;           // B*L rows
constexpr int KP1 = 224;           // K pad for E=200 (multiple of 32)
constexpr int KP2 = 768;

// ---- scratch (__device__ globals; no cudaMalloc allowed) ----
__device__ __align__(16) __half g_H[(size_t)M1 * Dd];   // fp16 H (attn-only consumer)
__device__ float g_C[Dd * Dd];
__device__ __align__(16) __half g_R[M2 * Dd];           // fp16 R (attn-only consumer)
__device__ float g_WTD[M2 * Dd];
__device__ __align__(16) __half gA1[(size_t)M1 * KP1];  // WE  fp16 (padded)
__device__ __align__(16) __half gB1[(size_t)Dd * KP1];  // Wt  fp16 (padded)
__device__ __align__(16) __half gA2[(size_t)M2 * KP2];  // LO fp16, then G fp16
__device__ __align__(16) __half gB2[(size_t)Dd * KP2];  // (AW@Ww)^T fp16
__device__ __align__(16) __half gB3[(size_t)Dd * KP2];  // Ww fp16

using u64 = unsigned long long;

// ===================== PTX helpers (compute_103-safe: sm_80+ subset) ========
__device__ __forceinline__ uint32_t smem_u32(const void* p) {
    uint32_t a;
    asm("{ .reg .u64 t; cvta.to.shared.u64 t, %1; cvt.u32.u64 %0, t; }"
        : "=r"(a) : "l"(p));
    return a;
}
__device__ __forceinline__ void cp16(uint32_t dst, const void* src) {
    asm volatile("cp.async.cg.shared.global [%0], [%1], 16;"
                 :: "r"(dst), "l"(src));
}
#define CP_COMMIT() asm volatile("cp.async.commit_group;" ::: "memory")
template <int N>
__device__ __forceinline__ void cp_wait() {
    asm volatile("cp.async.wait_group %0;" :: "n"(N) : "memory");
}
__device__ __forceinline__ void ldsm4(uint32_t& r0, uint32_t& r1,
                                      uint32_t& r2, uint32_t& r3, uint32_t a) {
    asm volatile("ldmatrix.sync.aligned.m8n8.x4.shared.b16 {%0,%1,%2,%3}, [%4];"
                 : "=r"(r0), "=r"(r1), "=r"(r2), "=r"(r3) : "r"(a));
}
__device__ __forceinline__ void mma_fp16(float* acc, const uint32_t* a,
                                         const uint32_t* b) {
    asm volatile(
        "mma.sync.aligned.m16n8k16.row.col.f32.f16.f16.f32 "
        "{%0,%1,%2,%3}, {%4,%5,%6,%7}, {%8,%9}, {%0,%1,%2,%3};"
        : "+f"(acc[0]), "+f"(acc[1]), "+f"(acc[2]), "+f"(acc[3])
        : "r"(a[0]), "r"(a[1]), "r"(a[2]), "r"(a[3]), "r"(b[0]), "r"(b[1]));
}

// ===================== Tensor-core GEMM (HMMA fp16, NT, 3-stage) ============
// Out[m,n] = act( sum_k A[m,k]*B[n,k] + bias[n] ), A [M,Kp], B [N,Kp] fp16.
// FM = m16-fragments per warp in M (4 -> BM=128, 2 -> BM=64). BN fixed 128.
// 8 warps (2m x 4n), 3-stage cp.async.
constexpr int SS = 40;        // SMEM row stride in fp16 (32 + 8 pad; 80B)
constexpr int STAGES = 3;
constexpr int hg_smem(int FM) { return (FM * 32 + 128) * SS * 2 * STAGES; }

template <int FM, bool DO_TANH, typename OutT>
__global__ void __launch_bounds__(256, 2)
hgemm_kernel(const __half* __restrict__ A, const __half* __restrict__ B,
             const float* __restrict__ bias, OutT* __restrict__ Out,
             int Kp, int Nglob)
{
    constexpr int BM = FM * 32;
    extern __shared__ __align__(16) char dynsmem[];
    __half* sA = reinterpret_cast<__half*>(dynsmem);
    __half* sB = sA + STAGES * BM * SS;

    const int tid = threadIdx.x, wid = tid >> 5, lane = tid & 31;
    const int wm = wid >> 2, wn = wid & 3;             // 2 x 4 warp grid
    const int m0 = blockIdx.y * BM, n0 = blockIdx.x * 128;
    const int NC = Kp / 32;

    uint32_t aBase[STAGES], bBase[STAGES];
#pragma unroll
    for (int s = 0; s < STAGES; s++) {
        aBase[s] = smem_u32(sA + s * BM * SS);
        bBase[s] = smem_u32(sB + s * 128 * SS);
    }

    // global->smem loader: 16B per row-chunk; 64 rows per pass
    const int lr = tid >> 2;           // row 0..63
    const int lc = tid & 3;            // 16B column chunk 0..3
    const uint32_t doff = (uint32_t)(lr * SS + lc * 8) * 2;
    auto load_tile = [&](int s, int kc) {
        const __half* ag = A + (size_t)(m0 + lr) * Kp + kc * 32 + lc * 8;
        const __half* bg = B + (size_t)(n0 + lr) * Kp + kc * 32 + lc * 8;
#pragma unroll
        for (int r = 0; r < BM; r += 64)
            cp16(aBase[s] + doff + r * SS * 2, ag + (size_t)r * Kp);
        cp16(bBase[s] + doff, bg);
        cp16(bBase[s] + doff + 64 * SS * 2, bg + (size_t)64 * Kp);
    };

    float acc[FM][4][4];
#pragma unroll
    for (int f = 0; f < FM; f++)
#pragma unroll
        for (int g = 0; g < 4; g++)
#pragma unroll
            for (int x = 0; x < 4; x++) acc[f][g][x] = 0.f;

    // ldmatrix address components (within a stage, in bytes)
    const uint32_t aRow = (uint32_t)(wm * FM * 16 + (lane & 15)) * SS * 2;
    const uint32_t aKof = (uint32_t)((lane >> 1) & 8) * 2;
    const uint32_t bRow =
        (uint32_t)(wn * 32 + ((lane >> 4) << 3) + (lane & 7)) * SS * 2;
    const uint32_t bKof = (uint32_t)(lane & 8) * 2;

    load_tile(0, 0); CP_COMMIT();
    load_tile(1, 1); CP_COMMIT();

    int buf = 0;
    for (int c = 0; c < NC; c++) {
        if (c + 1 < NC) cp_wait<1>(); else cp_wait<0>();
        __syncthreads();
        if (c + 2 < NC) { load_tile((buf + 2) % STAGES, c + 2); CP_COMMIT(); }

#pragma unroll
        for (int kk = 0; kk < 2; kk++) {
            uint32_t af[FM][4];
#pragma unroll
            for (int f = 0; f < FM; f++) {
                uint32_t addr = aBase[buf] + aRow + (uint32_t)(f * 16) * SS * 2 +
                                (uint32_t)(kk * 16) * 2 + aKof;
                ldsm4(af[f][0], af[f][1], af[f][2], af[f][3], addr);
            }
            uint32_t bf[4][2];
#pragma unroll
            for (int p = 0; p < 2; p++) {
                uint32_t addr = bBase[buf] + bRow + (uint32_t)(p * 16) * SS * 2 +
                                (uint32_t)(kk * 16) * 2 + bKof;
                ldsm4(bf[2 * p][0], bf[2 * p][1], bf[2 * p + 1][0],
                      bf[2 * p + 1][1], addr);
            }
#pragma unroll
            for (int f = 0; f < FM; f++)
#pragma unroll
                for (int g = 0; g < 4; g++)
                    mma_fp16(acc[f][g], af[f], bf[g]);
        }
        buf = (buf + 1) % STAGES;
    }

    // epilogue: c-frag m16n8 -> rows t/4, t/4+8; cols 2(t%4), +1
#pragma unroll
    for (int f = 0; f < FM; f++) {
        const int row0 = m0 + wm * FM * 16 + f * 16 + (lane >> 2);
#pragma unroll
        for (int g = 0; g < 4; g++) {
            const int col = n0 + wn * 32 + g * 8 + 2 * (lane & 3);
            float v0 = acc[f][g][0], v1 = acc[f][g][1];
            float v2 = acc[f][g][2], v3 = acc[f][g][3];
            if (bias) {
                const float b0 = bias[col], b1 = bias[col + 1];
                v0 += b0; v1 += b1; v2 += b0; v3 += b1;
            }
            if (DO_TANH) {
                v0 = tanhf(v0); v1 = tanhf(v1);
                v2 = tanhf(v2); v3 = tanhf(v3);
            }
            if (sizeof(OutT) == 2) {  // fp16 output
                __half2* o0 = reinterpret_cast<__half2*>(
                    (__half*)Out + (size_t)row0 * Nglob + col);
                __half2* o1 = reinterpret_cast<__half2*>(
                    (__half*)Out + (size_t)(row0 + 8) * Nglob + col);
                *o0 = __floats2half2_rn(v0, v1);
                *o1 = __floats2half2_rn(v2, v3);
            } else {
                *reinterpret_cast<float2*>(
                    (float*)Out + (size_t)row0 * Nglob + col) =
                    make_float2(v0, v1);
                *reinterpret_cast<float2*>(
                    (float*)Out + (size_t)(row0 + 8) * Nglob + col) =
                    make_float2(v2, v3);
            }
        }
    }
}

// ===================== fp32 -> fp16 convert (padded, optional transpose) ====
template <bool TRANS>
__global__ void cvt_kernel(const float* __restrict__ src,
                           __half* __restrict__ dst,
                           int Msz, int Ksrc, int Kpad)
{
    int idx = blockIdx.x * 256 + threadIdx.x;
    if (idx >= Msz * Kpad) return;
    int m = idx / Kpad, k = idx % Kpad;
    float x = 0.f;
    if (k < Ksrc)
        x = TRANS ? src[(size_t)k * Msz + m] : src[(size_t)m * Ksrc + k];
    dst[(size_t)m * Kpad + k] = __float2half_rn(x);
}

// ===================== fp32 SGEMM (tiny 768^3: C = attn_W @ Ww) =============
__device__ __forceinline__ void ffma2(u64& d, u64 a, u64 b) {
    asm("fma.rn.f32x2 %0, %1, %2, %0;" : "+l"(d) : "l"(a), "l"(b));
}
__device__ __forceinline__ u64 pack2f(float x, float y) {
    u64 r; asm("mov.b64 %0, {%1, %2};" : "=l"(r) : "f"(x), "f"(y)); return r;
}
__device__ __forceinline__ void unpack2f(u64 v, float& x, float& y) {
    asm("mov.b64 {%0, %1}, %2;" : "=f"(x), "=f"(y) : "l"(v));
}

__global__ void __launch_bounds__(256)
sgemm64_kernel(const float* __restrict__ A, const float* __restrict__ B,
               float* __restrict__ Cout, int N, int K)
{
    constexpr int BM = 64, BN = 64, BK = 16, TM = 4, TN = 4, TN2 = 2;
    __shared__ float As[BK][BM];
    __shared__ float Bs[BK][BN];
    const int tid = threadIdx.x;
    const int m0 = blockIdx.y * BM, n0 = blockIdx.x * BN;
    const int tx = tid % (BN / TN), ty = tid / (BN / TN);

    u64 acc2[TM][TN2];
#pragma unroll
    for (int i = 0; i < TM; i++)
#pragma unroll
        for (int j = 0; j < TN2; j++) acc2[i][j] = 0ull;

    for (int k0 = 0; k0 < K; k0 += BK) {
        {
            const int ar = tid / BK, ac = tid % BK;
#pragma unroll
            for (int i = 0; i < BM; i += 256 / BK)
                As[ac][ar + i] = A[(size_t)(m0 + ar + i) * K + (k0 + ac)];
        }
        {
            const int br = tid / BN, bc = tid % BN;
#pragma unroll
            for (int i = 0; i < BK; i += 256 / BN)
                Bs[br + i][bc] = B[(size_t)(k0 + br + i) * N + (n0 + bc)];
        }
        __syncthreads();
#pragma unroll
        for (int kk = 0; kk < BK; kk++) {
            float ra[TM];
            float4 va = *reinterpret_cast<const float4*>(&As[kk][ty * TM]);
            ra[0] = va.x; ra[1] = va.y; ra[2] = va.z; ra[3] = va.w;
            ulonglong2 vb = *reinterpret_cast<const ulonglong2*>(&Bs[kk][tx * TN]);
            u64 rb2[TN2] = {vb.x, vb.y};
#pragma unroll
            for (int i = 0; i < TM; i++) {
                const u64 a2 = pack2f(ra[i], ra[i]);
#pragma unroll
                for (int j = 0; j < TN2; j++) ffma2(acc2[i][j], a2, rb2[j]);
            }
        }
        __syncthreads();
    }
#pragma unroll
    for (int i = 0; i < TM; i++) {
        const int row = m0 + ty * TM + i;
#pragma unroll
        for (int j = 0; j < TN2; j++) {
            float v0, v1;
            unpack2f(acc2[i][j], v0, v1);
            const int col = n0 + tx * TN + 2 * j;
            *reinterpret_cast<float2*>(&Cout[(size_t)row * N + col]) =
                make_float2(v0, v1);
        }
    }
}

// ===================== attention (fp16 SMEM, 16B copies) ====================
__global__ void __launch_bounds__(256)
attn_kernel(const __half* __restrict__ H, const __half* __restrict__ R,
            __half* __restrict__ G)
{
    const int m = blockIdx.x, tid = threadIdx.x;
    const int wid = tid >> 5, lane = tid & 31;

    __shared__ __align__(16) __half sH[Wn * Dd];   // 12 KB
    __shared__ __align__(16) __half sR[Dd];        // 1.5 KB
    __shared__ float sAlpha[Wn];

    // 16B vectorized global -> smem staging
    const uint4* Hm4 = reinterpret_cast<const uint4*>(H + (size_t)m * Wn * Dd);
    const uint4* Rm4 = reinterpret_cast<const uint4*>(R + (size_t)m * Dd);
    uint4* sH4 = reinterpret_cast<uint4*>(sH);
    uint4* sR4 = reinterpret_cast<uint4*>(sR);
#pragma unroll
    for (int i = tid; i < Wn * Dd / 8; i += 256) sH4[i] = Hm4[i];
    if (tid < Dd / 8) sR4[tid] = Rm4[tid];
    __syncthreads();

    // warp 'wid' computes the dot for word 'wid' (half2 granularity)
    const __half2* Hw2 = reinterpret_cast<const __half2*>(sH + wid * Dd);
    const __half2* sR2 = reinterpret_cast<const __half2*>(sR);
    float s = 0.f;
    for (int i = lane; i < Dd / 2; i += 32) {
        float2 h = __half22float2(Hw2[i]);
        float2 r = __half22float2(sR2[i]);
        s = fmaf(h.x, r.x, s);
        s = fmaf(h.y, r.y, s);
    }
#pragma unroll
    for (int o = 16; o > 0; o >>= 1) s += __shfl_xor_sync(0xffffffffu, s, o);
    if (lane == 0) sAlpha[wid] = s;
    __syncthreads();

    float mx = -INFINITY;
#pragma unroll
    for (int w = 0; w < Wn; w++) mx = fmaxf(mx, sAlpha[w]);
    float a[Wn], den = 0.f;
#pragma unroll
    for (int w = 0; w < Wn; w++) { a[w] = expf(sAlpha[w] - mx); den += a[w]; }
    const float inv = 1.f / den;

    const __half2* sHall2 = reinterpret_cast<const __half2*>(sH);
    __half2* grow2 = reinterpret_cast<__half2*>(G + (size_t)m * KP2);
    for (int d = tid; d < Dd / 2; d += 256) {
        float gx = 0.f, gy = 0.f;
#pragma unroll
        for (int w = 0; w < Wn; w++) {
            float2 h = __half22float2(sHall2[w * (Dd / 2) + d]);
            gx = fmaf(a[w], h.x, gx);
            gy = fmaf(a[w], h.y, gy);
        }
        grow2[d] = __floats2half2_rn(gx * inv, gy * inv);
    }
}

// ===================== residual + LayerNorm =================================
__global__ void __launch_bounds__(256)
resid_ln_kernel(const float* __restrict__ LO, const float* __restrict__ WTD,
                const float* __restrict__ gamma, const float* __restrict__ beta,
                float* __restrict__ out)
{
    const int m = blockIdx.x, tid = threadIdx.x;
    const int wid = tid >> 5, lane = tid & 31;
    const float* lo = LO + (size_t)m * Dd;
    const float* wt = WTD + (size_t)m * Dd;

    float x[3], s = 0.f, ss = 0.f;
#pragma unroll
    for (int i = 0; i < 3; i++) {
        const int d = tid + i * 256;
        const float v = lo[d] + wt[d];
        x[i] = v; s += v; ss += v * v;
    }
    __shared__ float rs[8], rss[8];
#pragma unroll
    for (int o = 16; o > 0; o >>= 1) {
        s  += __shfl_xor_sync(0xffffffffu, s, o);
        ss += __shfl_xor_sync(0xffffffffu, ss, o);
    }
    if (lane == 0) { rs[wid] = s; rss[wid] = ss; }
    __syncthreads();
    s = 0.f; ss = 0.f;
#pragma unroll
    for (int w = 0; w < 8; w++) { s += rs[w]; ss += rss[w]; }
    const float mu = s * (1.f / Dd);
    const float var = ss * (1.f / Dd) - mu * mu;
    const float rstd = rsqrtf(var + 1e-12f);
#pragma unroll
    for (int i = 0; i < 3; i++) {
        const int d = tid + i * 256;
        out[(size_t)m * Dd + d] = (x[i] - mu) * rstd * gamma[d] + beta[d];
    }
}

// ===================== launch ===============================================
// Order chosen so launch #4 (the one ncu captures) is hgemm H.
extern "C" void kernel_launch(void* const* d_in, const int* in_sizes, int n_in,
                              void* d_out, int out_size)
{
    (void)in_sizes; (void)n_in; (void)out_size;
    const float* WE  = (const float*)d_in[0];
    const float* LO  = (const float*)d_in[1];
    const float* Wt  = (const float*)d_in[2];
    const float* bt  = (const float*)d_in[3];
    const float* Ww  = (const float*)d_in[4];
    const float* bw  = (const float*)d_in[5];
    const float* AW  = (const float*)d_in[6];
    const float* gam = (const float*)d_in[7];
    const float* bet = (const float*)d_in[8];
    float* out = (float*)d_out;

    float *pC, *pW;
    __half *pH, *pR, *pA1, *pB1, *pA2, *pB2, *pB3;
    cudaGetSymbolAddress((void**)&pH, g_H);
    cudaGetSymbolAddress((void**)&pC, g_C);
    cudaGetSymbolAddress((void**)&pR, g_R);
    cudaGetSymbolAddress((void**)&pW, g_WTD);
    cudaGetSymbolAddress((void**)&pA1, gA1);
    cudaGetSymbolAddress((void**)&pB1, gB1);
    cudaGetSymbolAddress((void**)&pA2, gA2);
    cudaGetSymbolAddress((void**)&pB2, gB2);
    cudaGetSymbolAddress((void**)&pB3, gB3);

    cudaFuncSetAttribute((const void*)hgemm_kernel<4, true, __half>,
                         cudaFuncAttributeMaxDynamicSharedMemorySize, hg_smem(4));
    cudaFuncSetAttribute((const void*)hgemm_kernel<2, false, __half>,
                         cudaFuncAttributeMaxDynamicSharedMemorySize, hg_smem(2));
    cudaFuncSetAttribute((const void*)hgemm_kernel<2, false, float>,
                         cudaFuncAttributeMaxDynamicSharedMemorySize, hg_smem(2));

    // 1-3: converts feeding hgemm H (+ LO for later)
    cvt_kernel<false><<<(M1 * KP1 + 255) / 256, 256>>>(WE, pA1, M1, Ee, KP1);
    cvt_kernel<false><<<(Dd * KP1 + 255) / 256, 256>>>(Wt, pB1, Dd, Ee, KP1);
    cvt_kernel<false><<<(M2 * KP2 + 255) / 256, 256>>>(LO, pA2, M2, Dd, KP2);

    // 4: H = tanh(WE @ Wt^T + bt)   [65536 x 768], K=224   <-- ncu capture
    hgemm_kernel<4, true, __half><<<dim3(Dd / 128, M1 / 128), 256, hg_smem(4)>>>(
        pA1, pB1, bt, pH, KP1, Dd);

    // 5-7: Ww convert, C = attn_W @ Ww (fp32), C^T convert
    cvt_kernel<false><<<(Dd * KP2 + 255) / 256, 256>>>(Ww, pB3, Dd, Dd, KP2);
    sgemm64_kernel<<<dim3(Dd / 64, Dd / 64), 256>>>(AW, Ww, pC, Dd, Dd);
    cvt_kernel<true><<<(Dd * KP2 + 255) / 256, 256>>>(pC, pB2, Dd, Dd, KP2);

    // 8: R = LO @ (attn_W@Ww)   [8192 x 768], K=768  (BM=64: better waves)
    hgemm_kernel<2, false, __half><<<dim3(Dd / 128, M2 / 64), 256, hg_smem(2)>>>(
        pA2, pB2, nullptr, pR, KP2, Dd);

    // 9: softmax attention -> fp16 G, reusing gA2
    attn_kernel<<<M2, 256>>>(pH, pR, pA2);

    // 10: WTD = G @ Ww^T + bw  (fp32 out, BM=64)
    hgemm_kernel<2, false, float><<<dim3(Dd / 128, M2 / 64), 256, hg_smem(2)>>>(
        pA2, pB3, bw, pW, KP2, Dd);

    // 11: out = LayerNorm(LO + WTD)
    resid_ln_kernel<<<M2, 256>>>(LO, pW, gam, bet, out);
}